// round 1
// baseline (speedup 1.0000x reference)
#include <cuda_runtime.h>

#define BSZ   4
#define TGT   512
#define KVLEN 4096
#define KVOLD (KVLEN - TGT)   /* 3584 */
#define EMB   2048
#define NH    16
#define HD    128
#define MROWS (BSZ * TGT)     /* 2048 */
#define QSCALE 0.08838834764831845f  /* 128^-0.5 */

/* scratch (static device arrays: allocation-free per harness rules) */
__device__ float g_q[MROWS * EMB];
__device__ float g_k[MROWS * EMB];
__device__ float g_v[MROWS * EMB];
__device__ float g_attn[MROWS * EMB];

/* ------------------------------------------------------------------ */
/* Fused QKV projection: y = x @ W^T + b  (NT gemm, both K-major)     */
/* grid.x = 48 (16 n-blocks each for q,k,v), grid.y = 16 (m-blocks)   */
/* ------------------------------------------------------------------ */
__global__ void __launch_bounds__(256) qkv_kernel(
    const float* __restrict__ x,
    const float* __restrict__ wq, const float* __restrict__ bq,
    const float* __restrict__ wk, const float* __restrict__ bk,
    const float* __restrict__ wv, const float* __restrict__ bv,
    float* __restrict__ okc, float* __restrict__ ovc, int write_cache)
{
    __shared__ float As[16][132];
    __shared__ float Bs[16][132];

    const int tid = threadIdx.x;
    const int tx = tid & 15, ty = tid >> 4;
    const int nb = blockIdx.x;       /* 0..47 */
    const int mb = blockIdx.y;       /* 0..15 */
    const int sel  = nb >> 4;        /* 0=q 1=k 2=v */
    const int nblk = nb & 15;

    const float* W    = (sel == 0) ? wq : (sel == 1) ? wk : wv;
    const float* bias = (sel == 0) ? bq : (sel == 1) ? bk : bv;

    const float* Ab = x + (size_t)(mb * 128) * EMB;
    const float* Bb = W + (size_t)(nblk * 128) * EMB;

    float acc[8][8] = {};

    for (int kt = 0; kt < EMB; kt += 16) {
        #pragma unroll
        for (int i = 0; i < 2; i++) {
            int fid = tid + i * 256;       /* 0..511 */
            int row = fid >> 2;            /* 0..127 */
            int k4  = (fid & 3) << 2;      /* 0,4,8,12 */
            float4 a4 = *(const float4*)(Ab + (size_t)row * EMB + kt + k4);
            As[k4 + 0][row] = a4.x; As[k4 + 1][row] = a4.y;
            As[k4 + 2][row] = a4.z; As[k4 + 3][row] = a4.w;
            float4 b4 = *(const float4*)(Bb + (size_t)row * EMB + kt + k4);
            Bs[k4 + 0][row] = b4.x; Bs[k4 + 1][row] = b4.y;
            Bs[k4 + 2][row] = b4.z; Bs[k4 + 3][row] = b4.w;
        }
        __syncthreads();
        #pragma unroll
        for (int k = 0; k < 16; k++) {
            float a[8], b[8];
            *(float4*)(a)     = *(const float4*)&As[k][ty * 8];
            *(float4*)(a + 4) = *(const float4*)&As[k][ty * 8 + 4];
            *(float4*)(b)     = *(const float4*)&Bs[k][tx * 8];
            *(float4*)(b + 4) = *(const float4*)&Bs[k][tx * 8 + 4];
            #pragma unroll
            for (int i = 0; i < 8; i++)
                #pragma unroll
                for (int j = 0; j < 8; j++)
                    acc[i][j] += a[i] * b[j];
        }
        __syncthreads();
    }

    #pragma unroll
    for (int i = 0; i < 8; i++) {
        int m = mb * 128 + ty * 8 + i;
        int bidx = m >> 9;          /* / TGT */
        int t    = m & 511;
        #pragma unroll
        for (int j = 0; j < 8; j++) {
            int n = nblk * 128 + tx * 8 + j;
            float v = acc[i][j] + bias[n];
            if (sel == 0) {
                g_q[(size_t)m * EMB + n] = v * QSCALE;
            } else {
                float* dst = (sel == 1) ? g_k : g_v;
                dst[(size_t)m * EMB + n] = v;
                if (write_cache) {
                    float* cd = (sel == 1) ? okc : ovc;
                    cd[((size_t)bidx * KVLEN + KVOLD + t) * EMB + n] = v;
                }
            }
        }
    }
}

/* ------------------------------------------------------------------ */
/* Output projection: out = g_attn @ wo^T + bo                         */
/* ------------------------------------------------------------------ */
__global__ void __launch_bounds__(256) proj_kernel(
    const float* __restrict__ wo, const float* __restrict__ bo,
    float* __restrict__ out)
{
    __shared__ float As[16][132];
    __shared__ float Bs[16][132];

    const int tid = threadIdx.x;
    const int tx = tid & 15, ty = tid >> 4;
    const int nblk = blockIdx.x;    /* 0..15 */
    const int mb   = blockIdx.y;    /* 0..15 */

    const float* Ab = g_attn + (size_t)(mb * 128) * EMB;
    const float* Bb = wo + (size_t)(nblk * 128) * EMB;

    float acc[8][8] = {};

    for (int kt = 0; kt < EMB; kt += 16) {
        #pragma unroll
        for (int i = 0; i < 2; i++) {
            int fid = tid + i * 256;
            int row = fid >> 2;
            int k4  = (fid & 3) << 2;
            float4 a4 = *(const float4*)(Ab + (size_t)row * EMB + kt + k4);
            As[k4 + 0][row] = a4.x; As[k4 + 1][row] = a4.y;
            As[k4 + 2][row] = a4.z; As[k4 + 3][row] = a4.w;
            float4 b4 = *(const float4*)(Bb + (size_t)row * EMB + kt + k4);
            Bs[k4 + 0][row] = b4.x; Bs[k4 + 1][row] = b4.y;
            Bs[k4 + 2][row] = b4.z; Bs[k4 + 3][row] = b4.w;
        }
        __syncthreads();
        #pragma unroll
        for (int k = 0; k < 16; k++) {
            float a[8], b[8];
            *(float4*)(a)     = *(const float4*)&As[k][ty * 8];
            *(float4*)(a + 4) = *(const float4*)&As[k][ty * 8 + 4];
            *(float4*)(b)     = *(const float4*)&Bs[k][tx * 8];
            *(float4*)(b + 4) = *(const float4*)&Bs[k][tx * 8 + 4];
            #pragma unroll
            for (int i = 0; i < 8; i++)
                #pragma unroll
                for (int j = 0; j < 8; j++)
                    acc[i][j] += a[i] * b[j];
        }
        __syncthreads();
    }

    #pragma unroll
    for (int i = 0; i < 8; i++) {
        int m = mb * 128 + ty * 8 + i;
        #pragma unroll
        for (int j = 0; j < 8; j++) {
            int n = nblk * 128 + tx * 8 + j;
            out[(size_t)m * EMB + n] = acc[i][j] + bo[n];
        }
    }
}

/* ------------------------------------------------------------------ */
/* Flash attention, fp32. grid = (8 q-tiles, 16 heads, 4 batch).       */
/* Q tile 64x128, KV tiles of 64. Online softmax stats in registers    */
/* (each 64-row block partitions rows by ty, reduced in half-warps).   */
/* KV rows < KVOLD come from the input caches; the rest from g_k/g_v.  */
/* ------------------------------------------------------------------ */
#define ATT_SMEM ((128 * 68 + 128 * 68 + 64 * 68) * 4)

__global__ void __launch_bounds__(256) attn_kernel(
    const float* __restrict__ kc_in, const float* __restrict__ vc_in,
    const float* __restrict__ mask)
{
    extern __shared__ float sm[];
    float* Qs = sm;                 /* [d*68 + i], 128 x 64 transposed */
    float* Ks = sm + 128 * 68;      /* K phase: [d*68+j]; V phase: [j*132+d] */
    float* Ps = sm + 2 * 128 * 68;  /* [i*68 + j] */

    const int tid = threadIdx.x;
    const int tx = tid & 15, ty = tid >> 4;
    const int qt = blockIdx.x, h = blockIdx.y, b = blockIdx.z;

    /* load Q tile transposed */
    {
        int i  = tid & 63;
        int dq = (tid >> 6) << 5;   /* 0,32,64,96 */
        const float* qp = g_q + (size_t)(b * TGT + qt * 64 + i) * EMB + h * HD + dq;
        #pragma unroll
        for (int d0 = 0; d0 < 32; d0 += 4) {
            float4 v = *(const float4*)(qp + d0);
            int d = dq + d0;
            Qs[(d + 0) * 68 + i] = v.x;
            Qs[(d + 1) * 68 + i] = v.y;
            Qs[(d + 2) * 68 + i] = v.z;
            Qs[(d + 3) * 68 + i] = v.w;
        }
    }

    float mr[4], lr[4], o[4][8];
    #pragma unroll
    for (int a = 0; a < 4; a++) {
        mr[a] = -1e30f; lr[a] = 0.f;
        #pragma unroll
        for (int c = 0; c < 8; c++) o[a][c] = 0.f;
    }

    for (int kt0 = 0; kt0 < KVLEN; kt0 += 64) {
        __syncthreads();            /* prev V consumed; Qs ready (first iter) */
        /* load K tile transposed */
        {
            int j  = tid & 63;
            int dq = (tid >> 6) << 5;
            const float* kp;
            if (kt0 < KVOLD)
                kp = kc_in + (size_t)(b * KVLEN + kt0 + j) * EMB + h * HD + dq;
            else
                kp = g_k + (size_t)(b * TGT + (kt0 - KVOLD) + j) * EMB + h * HD + dq;
            #pragma unroll
            for (int d0 = 0; d0 < 32; d0 += 4) {
                float4 v = *(const float4*)(kp + d0);
                int d = dq + d0;
                Ks[(d + 0) * 68 + j] = v.x;
                Ks[(d + 1) * 68 + j] = v.y;
                Ks[(d + 2) * 68 + j] = v.z;
                Ks[(d + 3) * 68 + j] = v.w;
            }
        }
        __syncthreads();

        /* S = Q K^T  (each thread: 4 rows x 4 cols) */
        float s[4][4];
        #pragma unroll
        for (int a = 0; a < 4; a++)
            #pragma unroll
            for (int c = 0; c < 4; c++) s[a][c] = 0.f;

        #pragma unroll 4
        for (int d = 0; d < 128; d++) {
            float4 qa = *(const float4*)&Qs[d * 68 + ty * 4];
            float4 kb = *(const float4*)&Ks[d * 68 + tx * 4];
            s[0][0] += qa.x * kb.x; s[0][1] += qa.x * kb.y; s[0][2] += qa.x * kb.z; s[0][3] += qa.x * kb.w;
            s[1][0] += qa.y * kb.x; s[1][1] += qa.y * kb.y; s[1][2] += qa.y * kb.z; s[1][3] += qa.y * kb.w;
            s[2][0] += qa.z * kb.x; s[2][1] += qa.z * kb.y; s[2][2] += qa.z * kb.z; s[2][3] += qa.z * kb.w;
            s[3][0] += qa.w * kb.x; s[3][1] += qa.w * kb.y; s[3][2] += qa.w * kb.z; s[3][3] += qa.w * kb.w;
        }

        /* additive attention mask */
        {
            const float* mrow = mask + (size_t)(qt * 64 + ty * 4) * KVLEN + kt0 + tx * 4;
            #pragma unroll
            for (int a = 0; a < 4; a++)
                #pragma unroll
                for (int c = 0; c < 4; c++)
                    s[a][c] += mrow[(size_t)a * KVLEN + c];
        }

        /* online softmax: each row lives in one 16-lane half-warp */
        float sc[4];
        #pragma unroll
        for (int a = 0; a < 4; a++) {
            float mx = fmaxf(fmaxf(s[a][0], s[a][1]), fmaxf(s[a][2], s[a][3]));
            #pragma unroll
            for (int off = 8; off > 0; off >>= 1)
                mx = fmaxf(mx, __shfl_xor_sync(0xffffffffu, mx, off, 16));
            float mn = fmaxf(mr[a], mx);
            sc[a] = __expf(mr[a] - mn);
            float p0 = __expf(s[a][0] - mn);
            float p1 = __expf(s[a][1] - mn);
            float p2 = __expf(s[a][2] - mn);
            float p3 = __expf(s[a][3] - mn);
            float rsum = p0 + p1 + p2 + p3;
            #pragma unroll
            for (int off = 8; off > 0; off >>= 1)
                rsum += __shfl_xor_sync(0xffffffffu, rsum, off, 16);
            lr[a] = lr[a] * sc[a] + rsum;
            mr[a] = mn;
            int i = ty * 4 + a;
            *(float4*)&Ps[i * 68 + tx * 4] = make_float4(p0, p1, p2, p3);
        }
        __syncthreads();            /* Ps ready, K buffer free */

        /* load V tile [j][d] into Ks buffer */
        {
            int idx = tid << 2;
            #pragma unroll
            for (int pass = 0; pass < 8; pass++) {
                int e = idx + pass * 1024;
                int j = e >> 7, d = e & 127;
                const float* vp;
                if (kt0 < KVOLD)
                    vp = vc_in + (size_t)(b * KVLEN + kt0 + j) * EMB + h * HD + d;
                else
                    vp = g_v + (size_t)(b * TGT + (kt0 - KVOLD) + j) * EMB + h * HD + d;
                *(float4*)&Ks[j * 132 + d] = *(const float4*)vp;
            }
        }
        __syncthreads();

        /* O = diag(sc) O + P V   (each thread: 4 rows x 8 dims) */
        #pragma unroll
        for (int a = 0; a < 4; a++)
            #pragma unroll
            for (int c = 0; c < 8; c++) o[a][c] *= sc[a];

        #pragma unroll 2
        for (int j = 0; j < 64; j++) {
            float4 v0 = *(const float4*)&Ks[j * 132 + tx * 8];
            float4 v1 = *(const float4*)&Ks[j * 132 + tx * 8 + 4];
            #pragma unroll
            for (int a = 0; a < 4; a++) {
                float p = Ps[(ty * 4 + a) * 68 + j];
                o[a][0] += p * v0.x; o[a][1] += p * v0.y;
                o[a][2] += p * v0.z; o[a][3] += p * v0.w;
                o[a][4] += p * v1.x; o[a][5] += p * v1.y;
                o[a][6] += p * v1.z; o[a][7] += p * v1.w;
            }
        }
    }

    /* write normalized output in [m][h*HD + d] (concat-heads) layout */
    #pragma unroll
    for (int a = 0; a < 4; a++) {
        float inv = 1.f / lr[a];
        int m = b * TGT + qt * 64 + ty * 4 + a;
        float* op = g_attn + (size_t)m * EMB + h * HD + tx * 8;
        float4 r0 = make_float4(o[a][0] * inv, o[a][1] * inv, o[a][2] * inv, o[a][3] * inv);
        float4 r1 = make_float4(o[a][4] * inv, o[a][5] * inv, o[a][6] * inv, o[a][7] * inv);
        *(float4*)op = r0;
        *(float4*)(op + 4) = r1;
    }
}

/* ------------------------------------------------------------------ */
extern "C" void kernel_launch(void* const* d_in, const int* in_sizes, int n_in,
                              void* d_out, int out_size)
{
    const float* x       = (const float*)d_in[0];
    const float* k_cache = (const float*)d_in[1];
    const float* v_cache = (const float*)d_in[2];
    const float* mask    = (const float*)d_in[3];
    const float* wq = (const float*)d_in[4];
    const float* bq = (const float*)d_in[5];
    const float* wk = (const float*)d_in[6];
    const float* bk = (const float*)d_in[7];
    const float* wv = (const float*)d_in[8];
    const float* bv = (const float*)d_in[9];
    const float* wo = (const float*)d_in[10];
    const float* bo = (const float*)d_in[11];

    float* out = (float*)d_out;
    long long need = (long long)MROWS * EMB + 2LL * BSZ * KVLEN * EMB;
    int write_cache = ((long long)out_size >= need) ? 1 : 0;
    float* okc = out + (size_t)MROWS * EMB;
    float* ovc = okc + (size_t)BSZ * KVLEN * EMB;

    cudaFuncSetAttribute(attn_kernel,
                         cudaFuncAttributeMaxDynamicSharedMemorySize, ATT_SMEM);

    if (write_cache) {
        size_t bytes = (size_t)KVOLD * EMB * sizeof(float);
        for (int bb = 0; bb < BSZ; bb++) {
            cudaMemcpyAsync(okc + (size_t)bb * KVLEN * EMB,
                            k_cache + (size_t)bb * KVLEN * EMB,
                            bytes, cudaMemcpyDeviceToDevice, 0);
            cudaMemcpyAsync(ovc + (size_t)bb * KVLEN * EMB,
                            v_cache + (size_t)bb * KVLEN * EMB,
                            bytes, cudaMemcpyDeviceToDevice, 0);
        }
    }

    qkv_kernel<<<dim3(48, 16), 256>>>(x, wq, bq, wk, bk, wv, bv,
                                      okc, ovc, write_cache);
    attn_kernel<<<dim3(8, 16, 4), 256, ATT_SMEM>>>(k_cache, v_cache, mask);
    proj_kernel<<<dim3(16, 16), 256>>>(wo, bo, out);
}

// round 2
// speedup vs baseline: 1.8636x; 1.8636x over previous
#include <cuda_runtime.h>

#define BSZ   4
#define TGT   512
#define KVLEN 4096
#define KVOLD (KVLEN - TGT)   /* 3584 */
#define EMB   2048
#define NH    16
#define HD    128
#define MROWS (BSZ * TGT)     /* 2048 */
#define QSCALE 0.08838834764831845f  /* 128^-0.5 */

/* scratch (static device arrays: allocation-free per harness rules) */
__device__ float g_q[MROWS * EMB];
__device__ float g_k[MROWS * EMB];
__device__ float g_v[MROWS * EMB];
__device__ float g_attn[MROWS * EMB];

__device__ __forceinline__ unsigned f2tf(float f) {
    unsigned u;
    asm("cvt.rna.tf32.f32 %0, %1;" : "=r"(u) : "f"(f));
    return u;
}

__device__ __forceinline__ void mma_tf32(float c[4], const unsigned a[4], const unsigned b[2]) {
    asm("mma.sync.aligned.m16n8k8.row.col.f32.tf32.tf32.f32 "
        "{%0,%1,%2,%3},{%4,%5,%6,%7},{%8,%9},{%0,%1,%2,%3};"
        : "+f"(c[0]), "+f"(c[1]), "+f"(c[2]), "+f"(c[3])
        : "r"(a[0]), "r"(a[1]), "r"(a[2]), "r"(a[3]), "r"(b[0]), "r"(b[1]));
}

/* ------------------------------------------------------------------ */
/* tf32 NT GEMM core: C[128,128] tile of A[M,K] @ B[N,K]^T            */
/* block 256 thr = 8 warps (2 m x 4 n), warp tile 64x32               */
/* ------------------------------------------------------------------ */
#define LDA 36   /* smem row stride (floats), 144B = 16B-aligned, conflict-free */

/* Fused QKV: grid.x = 48 (16 n-blocks for each of q,k,v), grid.y = 16 */
__global__ void __launch_bounds__(256) qkv_kernel(
    const float* __restrict__ x,
    const float* __restrict__ wq, const float* __restrict__ bq,
    const float* __restrict__ wk, const float* __restrict__ bk,
    const float* __restrict__ wv, const float* __restrict__ bv,
    float* __restrict__ okc, float* __restrict__ ovc, int write_cache)
{
    __shared__ unsigned As[128][LDA];
    __shared__ unsigned Bs[128][LDA];

    const int tid  = threadIdx.x;
    const int lane = tid & 31, wid = tid >> 5;
    const int g = lane >> 2, tg = lane & 3;
    const int wm = wid >> 2, wn = wid & 3;

    const int nb = blockIdx.x;
    const int mb = blockIdx.y;
    const int sel  = nb >> 4;        /* 0=q 1=k 2=v */
    const int nblk = nb & 15;

    const float* W    = (sel == 0) ? wq : (sel == 1) ? wk : wv;
    const float* bias = (sel == 0) ? bq : (sel == 1) ? bk : bv;
    const float* Ab = x + (size_t)(mb * 128) * EMB;
    const float* Bb = W + (size_t)(nblk * 128) * EMB;

    float c[4][4][4] = {};

    for (int kt = 0; kt < EMB / 32; kt++) {
        #pragma unroll
        for (int t = 0; t < 4; t++) {
            int idx = tid + t * 256;
            int row = idx >> 3;
            int c4  = (idx & 7) << 2;
            float4 a4 = *(const float4*)(Ab + (size_t)row * EMB + kt * 32 + c4);
            As[row][c4 + 0] = f2tf(a4.x); As[row][c4 + 1] = f2tf(a4.y);
            As[row][c4 + 2] = f2tf(a4.z); As[row][c4 + 3] = f2tf(a4.w);
            float4 b4 = *(const float4*)(Bb + (size_t)row * EMB + kt * 32 + c4);
            Bs[row][c4 + 0] = f2tf(b4.x); Bs[row][c4 + 1] = f2tf(b4.y);
            Bs[row][c4 + 2] = f2tf(b4.z); Bs[row][c4 + 3] = f2tf(b4.w);
        }
        __syncthreads();

        #pragma unroll
        for (int ks = 0; ks < 4; ks++) {
            int k0 = ks * 8 + tg;
            unsigned a[4][4], b[4][2];
            #pragma unroll
            for (int mt = 0; mt < 4; mt++) {
                int r = wm * 64 + mt * 16 + g;
                a[mt][0] = As[r][k0];     a[mt][1] = As[r + 8][k0];
                a[mt][2] = As[r][k0 + 4]; a[mt][3] = As[r + 8][k0 + 4];
            }
            #pragma unroll
            for (int nt = 0; nt < 4; nt++) {
                int n = wn * 32 + nt * 8 + g;
                b[nt][0] = Bs[n][k0]; b[nt][1] = Bs[n][k0 + 4];
            }
            #pragma unroll
            for (int mt = 0; mt < 4; mt++)
                #pragma unroll
                for (int nt = 0; nt < 4; nt++)
                    mma_tf32(c[mt][nt], a[mt], b[nt]);
        }
        __syncthreads();
    }

    #pragma unroll
    for (int mt = 0; mt < 4; mt++) {
        #pragma unroll
        for (int nt = 0; nt < 4; nt++) {
            int col = nblk * 128 + wn * 32 + nt * 8 + 2 * tg;
            #pragma unroll
            for (int half = 0; half < 2; half++) {
                int m = mb * 128 + wm * 64 + mt * 16 + g + half * 8;
                float v0 = c[mt][nt][half * 2 + 0] + bias[col];
                float v1 = c[mt][nt][half * 2 + 1] + bias[col + 1];
                if (sel == 0) {
                    g_q[(size_t)m * EMB + col]     = v0 * QSCALE;
                    g_q[(size_t)m * EMB + col + 1] = v1 * QSCALE;
                } else {
                    float* dst = (sel == 1) ? g_k : g_v;
                    dst[(size_t)m * EMB + col]     = v0;
                    dst[(size_t)m * EMB + col + 1] = v1;
                    if (write_cache) {
                        int bidx = m >> 9, t = m & 511;
                        float* cd = (sel == 1) ? okc : ovc;
                        size_t o = ((size_t)bidx * KVLEN + KVOLD + t) * EMB + col;
                        cd[o] = v0; cd[o + 1] = v1;
                    }
                }
            }
        }
    }
}

/* Output projection: out = g_attn @ wo^T + bo. grid (16,16) */
__global__ void __launch_bounds__(256) proj_kernel(
    const float* __restrict__ wo, const float* __restrict__ bo,
    float* __restrict__ out)
{
    __shared__ unsigned As[128][LDA];
    __shared__ unsigned Bs[128][LDA];

    const int tid  = threadIdx.x;
    const int lane = tid & 31, wid = tid >> 5;
    const int g = lane >> 2, tg = lane & 3;
    const int wm = wid >> 2, wn = wid & 3;
    const int nblk = blockIdx.x, mb = blockIdx.y;

    const float* Ab = g_attn + (size_t)(mb * 128) * EMB;
    const float* Bb = wo + (size_t)(nblk * 128) * EMB;

    float c[4][4][4] = {};

    for (int kt = 0; kt < EMB / 32; kt++) {
        #pragma unroll
        for (int t = 0; t < 4; t++) {
            int idx = tid + t * 256;
            int row = idx >> 3;
            int c4  = (idx & 7) << 2;
            float4 a4 = *(const float4*)(Ab + (size_t)row * EMB + kt * 32 + c4);
            As[row][c4 + 0] = f2tf(a4.x); As[row][c4 + 1] = f2tf(a4.y);
            As[row][c4 + 2] = f2tf(a4.z); As[row][c4 + 3] = f2tf(a4.w);
            float4 b4 = *(const float4*)(Bb + (size_t)row * EMB + kt * 32 + c4);
            Bs[row][c4 + 0] = f2tf(b4.x); Bs[row][c4 + 1] = f2tf(b4.y);
            Bs[row][c4 + 2] = f2tf(b4.z); Bs[row][c4 + 3] = f2tf(b4.w);
        }
        __syncthreads();

        #pragma unroll
        for (int ks = 0; ks < 4; ks++) {
            int k0 = ks * 8 + tg;
            unsigned a[4][4], b[4][2];
            #pragma unroll
            for (int mt = 0; mt < 4; mt++) {
                int r = wm * 64 + mt * 16 + g;
                a[mt][0] = As[r][k0];     a[mt][1] = As[r + 8][k0];
                a[mt][2] = As[r][k0 + 4]; a[mt][3] = As[r + 8][k0 + 4];
            }
            #pragma unroll
            for (int nt = 0; nt < 4; nt++) {
                int n = wn * 32 + nt * 8 + g;
                b[nt][0] = Bs[n][k0]; b[nt][1] = Bs[n][k0 + 4];
            }
            #pragma unroll
            for (int mt = 0; mt < 4; mt++)
                #pragma unroll
                for (int nt = 0; nt < 4; nt++)
                    mma_tf32(c[mt][nt], a[mt], b[nt]);
        }
        __syncthreads();
    }

    #pragma unroll
    for (int mt = 0; mt < 4; mt++)
        #pragma unroll
        for (int nt = 0; nt < 4; nt++) {
            int col = nblk * 128 + wn * 32 + nt * 8 + 2 * tg;
            #pragma unroll
            for (int half = 0; half < 2; half++) {
                int m = mb * 128 + wm * 64 + mt * 16 + g + half * 8;
                out[(size_t)m * EMB + col]     = c[mt][nt][half * 2 + 0] + bo[col];
                out[(size_t)m * EMB + col + 1] = c[mt][nt][half * 2 + 1] + bo[col + 1];
            }
        }
}

/* ------------------------------------------------------------------ */
/* Flash attention with tf32 mma. grid (8 q-tiles, 16 heads, 4 batch). */
/* Q tile 64x128, KV tile 64. 8 warps as (4 m x 2 n).                  */
/* ------------------------------------------------------------------ */
#define LQ 132   /* Qs/Ks row stride (tf32 words) */
#define LV 68    /* Vs/Ps row stride */
#define ATT_SMEM ((64 * LQ + 64 * LQ + 128 * LV + 64 * LV) * 4)

__global__ void __launch_bounds__(256) attn_kernel(
    const float* __restrict__ kc_in, const float* __restrict__ vc_in,
    const float* __restrict__ mask)
{
    extern __shared__ unsigned smu[];
    unsigned* Qs = smu;                       /* [64][LQ]  tf32 */
    unsigned* Ks = Qs + 64 * LQ;              /* [64][LQ]  tf32 (j-major) */
    unsigned* Vs = Ks + 64 * LQ;              /* [128][LV] tf32 (d-major, j contiguous) */
    unsigned* Ps = Vs + 128 * LV;             /* [64][LV]  tf32 */

    __shared__ float m_row[64], l_row[64], sc_row[64];
    __shared__ float pmax[2][64], psum[2][64];

    const int tid  = threadIdx.x;
    const int lane = tid & 31, wid = tid >> 5;
    const int g = lane >> 2, tg = lane & 3;
    const int wm = wid >> 1, wn = wid & 1;    /* same split for S and PV */
    const int qt = blockIdx.x, h = blockIdx.y, b = blockIdx.z;

    const int r0 = wm * 16 + g;
    const int r1 = r0 + 8;

    /* load Q tile (tf32) */
    #pragma unroll
    for (int t = 0; t < 8; t++) {
        int idx = tid + t * 256;
        int row = idx >> 5;
        int d4  = (idx & 31) << 2;
        float4 v = *(const float4*)(g_q + (size_t)(b * TGT + qt * 64 + row) * EMB + h * HD + d4);
        Qs[row * LQ + d4 + 0] = f2tf(v.x); Qs[row * LQ + d4 + 1] = f2tf(v.y);
        Qs[row * LQ + d4 + 2] = f2tf(v.z); Qs[row * LQ + d4 + 3] = f2tf(v.w);
    }
    if (tid < 64) { m_row[tid] = -1e30f; l_row[tid] = 0.f; }

    float o[8][4];
    #pragma unroll
    for (int nt = 0; nt < 8; nt++)
        #pragma unroll
        for (int i = 0; i < 4; i++) o[nt][i] = 0.f;

    for (int kt0 = 0; kt0 < KVLEN; kt0 += 64) {
        __syncthreads();   /* Q ready / prev iter's K,V consumed */

        /* load K tile [j][d] and V tile transposed [d][j] */
        const float* ksrc = (kt0 < KVOLD)
            ? kc_in + (size_t)(b * KVLEN + kt0) * EMB + h * HD
            : g_k + (size_t)(b * TGT + (kt0 - KVOLD)) * EMB + h * HD;
        const float* vsrc = (kt0 < KVOLD)
            ? vc_in + (size_t)(b * KVLEN + kt0) * EMB + h * HD
            : g_v + (size_t)(b * TGT + (kt0 - KVOLD)) * EMB + h * HD;
        #pragma unroll
        for (int t = 0; t < 8; t++) {
            int idx = tid + t * 256;
            int j  = idx >> 5;
            int d4 = (idx & 31) << 2;
            float4 kv = *(const float4*)(ksrc + (size_t)j * EMB + d4);
            Ks[j * LQ + d4 + 0] = f2tf(kv.x); Ks[j * LQ + d4 + 1] = f2tf(kv.y);
            Ks[j * LQ + d4 + 2] = f2tf(kv.z); Ks[j * LQ + d4 + 3] = f2tf(kv.w);
            float4 vv = *(const float4*)(vsrc + (size_t)j * EMB + d4);
            Vs[(d4 + 0) * LV + j] = f2tf(vv.x); Vs[(d4 + 1) * LV + j] = f2tf(vv.y);
            Vs[(d4 + 2) * LV + j] = f2tf(vv.z); Vs[(d4 + 3) * LV + j] = f2tf(vv.w);
        }
        __syncthreads();

        /* S = Q K^T : warp tile m16 x n32 */
        const int cb = wn * 32;
        float s[4][4];
        #pragma unroll
        for (int nt = 0; nt < 4; nt++)
            #pragma unroll
            for (int i = 0; i < 4; i++) s[nt][i] = 0.f;

        #pragma unroll
        for (int ks = 0; ks < 16; ks++) {
            int k0 = ks * 8 + tg;
            unsigned a[4];
            a[0] = Qs[r0 * LQ + k0];     a[1] = Qs[r1 * LQ + k0];
            a[2] = Qs[r0 * LQ + k0 + 4]; a[3] = Qs[r1 * LQ + k0 + 4];
            #pragma unroll
            for (int nt = 0; nt < 4; nt++) {
                int n = cb + nt * 8 + g;
                unsigned bb[2] = { Ks[n * LQ + k0], Ks[n * LQ + k0 + 4] };
                mma_tf32(s[nt], a, bb);
            }
        }

        /* + mask */
        {
            const float* mrow = mask + (size_t)(qt * 64) * KVLEN + kt0;
            #pragma unroll
            for (int nt = 0; nt < 4; nt++) {
                int col = cb + nt * 8 + 2 * tg;
                s[nt][0] += mrow[(size_t)r0 * KVLEN + col];
                s[nt][1] += mrow[(size_t)r0 * KVLEN + col + 1];
                s[nt][2] += mrow[(size_t)r1 * KVLEN + col];
                s[nt][3] += mrow[(size_t)r1 * KVLEN + col + 1];
            }
        }

        /* partial row max (4 lanes own a row) */
        float mx0 = -1e30f, mx1 = -1e30f;
        #pragma unroll
        for (int nt = 0; nt < 4; nt++) {
            mx0 = fmaxf(mx0, fmaxf(s[nt][0], s[nt][1]));
            mx1 = fmaxf(mx1, fmaxf(s[nt][2], s[nt][3]));
        }
        mx0 = fmaxf(mx0, __shfl_xor_sync(0xffffffffu, mx0, 1));
        mx0 = fmaxf(mx0, __shfl_xor_sync(0xffffffffu, mx0, 2));
        mx1 = fmaxf(mx1, __shfl_xor_sync(0xffffffffu, mx1, 1));
        mx1 = fmaxf(mx1, __shfl_xor_sync(0xffffffffu, mx1, 2));
        if (tg == 0) { pmax[wn][r0] = mx0; pmax[wn][r1] = mx1; }
        __syncthreads();

        float mn0 = fmaxf(m_row[r0], fmaxf(pmax[0][r0], pmax[1][r0]));
        float mn1 = fmaxf(m_row[r1], fmaxf(pmax[0][r1], pmax[1][r1]));
        float s0 = 0.f, s1 = 0.f;
        #pragma unroll
        for (int nt = 0; nt < 4; nt++) {
            s[nt][0] = __expf(s[nt][0] - mn0);
            s[nt][1] = __expf(s[nt][1] - mn0);
            s[nt][2] = __expf(s[nt][2] - mn1);
            s[nt][3] = __expf(s[nt][3] - mn1);
            s0 += s[nt][0] + s[nt][1];
            s1 += s[nt][2] + s[nt][3];
            int col = cb + nt * 8 + 2 * tg;
            Ps[r0 * LV + col]     = f2tf(s[nt][0]);
            Ps[r0 * LV + col + 1] = f2tf(s[nt][1]);
            Ps[r1 * LV + col]     = f2tf(s[nt][2]);
            Ps[r1 * LV + col + 1] = f2tf(s[nt][3]);
        }
        s0 += __shfl_xor_sync(0xffffffffu, s0, 1);
        s0 += __shfl_xor_sync(0xffffffffu, s0, 2);
        s1 += __shfl_xor_sync(0xffffffffu, s1, 1);
        s1 += __shfl_xor_sync(0xffffffffu, s1, 2);
        if (tg == 0) { psum[wn][r0] = s0; psum[wn][r1] = s1; }
        __syncthreads();

        /* warp 0 updates the running stats */
        if (wid == 0) {
            #pragma unroll
            for (int t = 0; t < 2; t++) {
                int rr = lane + t * 32;
                float mnn = fmaxf(m_row[rr], fmaxf(pmax[0][rr], pmax[1][rr]));
                float scc = __expf(m_row[rr] - mnn);
                l_row[rr] = l_row[rr] * scc + psum[0][rr] + psum[1][rr];
                m_row[rr] = mnn;
                sc_row[rr] = scc;
            }
        }
        __syncthreads();

        /* O = diag(sc) O + P V : warp tile m16 x n64 */
        float sc0 = sc_row[r0], sc1 = sc_row[r1];
        #pragma unroll
        for (int nt = 0; nt < 8; nt++) {
            o[nt][0] *= sc0; o[nt][1] *= sc0;
            o[nt][2] *= sc1; o[nt][3] *= sc1;
        }
        #pragma unroll
        for (int ks = 0; ks < 8; ks++) {
            int k0 = ks * 8 + tg;
            unsigned a[4];
            a[0] = Ps[r0 * LV + k0];     a[1] = Ps[r1 * LV + k0];
            a[2] = Ps[r0 * LV + k0 + 4]; a[3] = Ps[r1 * LV + k0 + 4];
            #pragma unroll
            for (int nt = 0; nt < 8; nt++) {
                int n = wn * 64 + nt * 8 + g;
                unsigned bb[2] = { Vs[n * LV + k0], Vs[n * LV + k0 + 4] };
                mma_tf32(o[nt], a, bb);
            }
        }
    }

    /* normalize + write (concat-heads layout) */
    float inv0 = 1.f / l_row[r0];
    float inv1 = 1.f / l_row[r1];
    int row0 = b * TGT + qt * 64 + r0;
    int row1 = b * TGT + qt * 64 + r1;
    #pragma unroll
    for (int nt = 0; nt < 8; nt++) {
        int col = wn * 64 + nt * 8 + 2 * tg;
        g_attn[(size_t)row0 * EMB + h * HD + col]     = o[nt][0] * inv0;
        g_attn[(size_t)row0 * EMB + h * HD + col + 1] = o[nt][1] * inv0;
        g_attn[(size_t)row1 * EMB + h * HD + col]     = o[nt][2] * inv1;
        g_attn[(size_t)row1 * EMB + h * HD + col + 1] = o[nt][3] * inv1;
    }
}

/* ------------------------------------------------------------------ */
extern "C" void kernel_launch(void* const* d_in, const int* in_sizes, int n_in,
                              void* d_out, int out_size)
{
    const float* x       = (const float*)d_in[0];
    const float* k_cache = (const float*)d_in[1];
    const float* v_cache = (const float*)d_in[2];
    const float* mask    = (const float*)d_in[3];
    const float* wq = (const float*)d_in[4];
    const float* bq = (const float*)d_in[5];
    const float* wk = (const float*)d_in[6];
    const float* bk = (const float*)d_in[7];
    const float* wv = (const float*)d_in[8];
    const float* bv = (const float*)d_in[9];
    const float* wo = (const float*)d_in[10];
    const float* bo = (const float*)d_in[11];

    float* out = (float*)d_out;
    long long need = (long long)MROWS * EMB + 2LL * BSZ * KVLEN * EMB;
    int write_cache = ((long long)out_size >= need) ? 1 : 0;
    float* okc = out + (size_t)MROWS * EMB;
    float* ovc = okc + (size_t)BSZ * KVLEN * EMB;

    cudaFuncSetAttribute(attn_kernel,
                         cudaFuncAttributeMaxDynamicSharedMemorySize, ATT_SMEM);

    if (write_cache) {
        size_t bytes = (size_t)KVOLD * EMB * sizeof(float);
        for (int bb = 0; bb < BSZ; bb++) {
            cudaMemcpyAsync(okc + (size_t)bb * KVLEN * EMB,
                            k_cache + (size_t)bb * KVLEN * EMB,
                            bytes, cudaMemcpyDeviceToDevice, 0);
            cudaMemcpyAsync(ovc + (size_t)bb * KVLEN * EMB,
                            v_cache + (size_t)bb * KVLEN * EMB,
                            bytes, cudaMemcpyDeviceToDevice, 0);
        }
    }

    qkv_kernel<<<dim3(48, 16), 256>>>(x, wq, bq, wk, bk, wv, bv,
                                      okc, ovc, write_cache);
    attn_kernel<<<dim3(8, 16, 4), 256, ATT_SMEM>>>(k_cache, v_cache, mask);
    proj_kernel<<<dim3(16, 16), 256>>>(wo, bo, out);
}

// round 3
// speedup vs baseline: 2.9639x; 1.5904x over previous
#include <cuda_runtime.h>

#define BSZ   4
#define TGT   512
#define KVLEN 4096
#define KVOLD (KVLEN - TGT)   /* 3584 */
#define EMB   2048
#define NH    16
#define HD    128
#define MROWS (BSZ * TGT)     /* 2048 */
#define QSCALE 0.08838834764831845f  /* 128^-0.5 */

/* scratch (static device arrays: allocation-free per harness rules) */
__device__ float g_q[MROWS * EMB];
__device__ float g_k[MROWS * EMB];
__device__ float g_v[MROWS * EMB];
__device__ float g_attn[MROWS * EMB];

__device__ __forceinline__ unsigned f2tf(float f) {
    unsigned u;
    asm("cvt.rna.tf32.f32 %0, %1;" : "=r"(u) : "f"(f));
    return u;
}

__device__ __forceinline__ void mma_tf32(float c[4], const unsigned a[4], const unsigned b[2]) {
    asm("mma.sync.aligned.m16n8k8.row.col.f32.tf32.tf32.f32 "
        "{%0,%1,%2,%3},{%4,%5,%6,%7},{%8,%9},{%0,%1,%2,%3};"
        : "+f"(c[0]), "+f"(c[1]), "+f"(c[2]), "+f"(c[3])
        : "r"(a[0]), "r"(a[1]), "r"(a[2]), "r"(a[3]), "r"(b[0]), "r"(b[1]));
}

__device__ __forceinline__ unsigned sm_u32(const void* p) {
    return (unsigned)__cvta_generic_to_shared(p);
}
__device__ __forceinline__ void cp16(unsigned dst, const void* src) {
    asm volatile("cp.async.cg.shared.global [%0], [%1], 16;" :: "r"(dst), "l"(src));
}
#define CP_COMMIT() asm volatile("cp.async.commit_group;")
#define CP_WAIT(n)  asm volatile("cp.async.wait_group %0;" :: "n"(n))
#define BAR_PAIR(id) asm volatile("bar.sync %0, 64;" :: "r"(id) : "memory")

/* ================================================================== */
/* tf32 NT GEMM mainloop: 128x128 tile, k-depth 32, 3-stage cp.async  */
/* raw f32 in smem, cvt at fragment load (same rna rounding).         */
/* block = 256 threads (8 warps, 2m x 4n), smem = 2*3*128*36*4B       */
/* ================================================================== */
#define GLD 36
#define GST (128 * GLD)          /* 4608 floats per stage */
#define GEMM_SMEM (2 * 3 * GST * 4)

__device__ __forceinline__ void gemm_main(
    const float* __restrict__ Ab, const float* __restrict__ Bb,
    float c[4][4][4], float* As, float* Bs, int tid)
{
    const int lane = tid & 31, wid = tid >> 5;
    const int g = lane >> 2, tg = lane & 3;
    const int wm = wid >> 2, wn = wid & 3;

    /* prime stages 0,1 */
    #pragma unroll
    for (int s = 0; s < 2; s++) {
        #pragma unroll
        for (int p = 0; p < 4; p++) {
            int cc = tid + p * 256;
            int row = cc >> 3, off = (cc & 7) << 2;
            cp16(sm_u32(As + s * GST + row * GLD + off),
                 Ab + (size_t)row * EMB + s * 32 + off);
            cp16(sm_u32(Bs + s * GST + row * GLD + off),
                 Bb + (size_t)row * EMB + s * 32 + off);
        }
        CP_COMMIT();
    }

    for (int kt = 0; kt < EMB / 32; kt++) {
        if (kt < EMB / 32 - 1) CP_WAIT(1); else CP_WAIT(0);
        __syncthreads();                 /* stage kt ready; MMA(kt-1) done everywhere */

        if (kt + 2 < EMB / 32) {
            int s3 = (kt + 2) % 3;
            #pragma unroll
            for (int p = 0; p < 4; p++) {
                int cc = tid + p * 256;
                int row = cc >> 3, off = (cc & 7) << 2;
                cp16(sm_u32(As + s3 * GST + row * GLD + off),
                     Ab + (size_t)row * EMB + (kt + 2) * 32 + off);
                cp16(sm_u32(Bs + s3 * GST + row * GLD + off),
                     Bb + (size_t)row * EMB + (kt + 2) * 32 + off);
            }
            CP_COMMIT();
        }

        const float* Af = As + (kt % 3) * GST;
        const float* Bf = Bs + (kt % 3) * GST;
        #pragma unroll
        for (int ks = 0; ks < 4; ks++) {
            int k0 = ks * 8 + tg;
            unsigned a[4][4], b[4][2];
            #pragma unroll
            for (int mt = 0; mt < 4; mt++) {
                int r = wm * 64 + mt * 16 + g;
                a[mt][0] = f2tf(Af[r * GLD + k0]);
                a[mt][1] = f2tf(Af[(r + 8) * GLD + k0]);
                a[mt][2] = f2tf(Af[r * GLD + k0 + 4]);
                a[mt][3] = f2tf(Af[(r + 8) * GLD + k0 + 4]);
            }
            #pragma unroll
            for (int nt = 0; nt < 4; nt++) {
                int n = wn * 32 + nt * 8 + g;
                b[nt][0] = f2tf(Bf[n * GLD + k0]);
                b[nt][1] = f2tf(Bf[n * GLD + k0 + 4]);
            }
            #pragma unroll
            for (int mt = 0; mt < 4; mt++)
                #pragma unroll
                for (int nt = 0; nt < 4; nt++)
                    mma_tf32(c[mt][nt], a[mt], b[nt]);
        }
    }
}

/* Fused QKV: grid.x = 48 (16 n-blocks for each of q,k,v), grid.y = 16 */
__global__ void __launch_bounds__(256, 2) qkv_kernel(
    const float* __restrict__ x,
    const float* __restrict__ wq, const float* __restrict__ bq,
    const float* __restrict__ wk, const float* __restrict__ bk,
    const float* __restrict__ wv, const float* __restrict__ bv,
    float* __restrict__ okc, float* __restrict__ ovc, int write_cache)
{
    extern __shared__ float gsm[];
    float* As = gsm;
    float* Bs = gsm + 3 * GST;

    const int tid  = threadIdx.x;
    const int lane = tid & 31, wid = tid >> 5;
    const int g = lane >> 2, tg = lane & 3;
    const int wm = wid >> 2, wn = wid & 3;

    const int nb = blockIdx.x, mb = blockIdx.y;
    const int sel = nb >> 4, nblk = nb & 15;

    const float* W    = (sel == 0) ? wq : (sel == 1) ? wk : wv;
    const float* bias = (sel == 0) ? bq : (sel == 1) ? bk : bv;

    float c[4][4][4] = {};
    gemm_main(x + (size_t)(mb * 128) * EMB, W + (size_t)(nblk * 128) * EMB,
              c, As, Bs, tid);

    #pragma unroll
    for (int mt = 0; mt < 4; mt++) {
        #pragma unroll
        for (int nt = 0; nt < 4; nt++) {
            int col = nblk * 128 + wn * 32 + nt * 8 + 2 * tg;
            #pragma unroll
            for (int half = 0; half < 2; half++) {
                int m = mb * 128 + wm * 64 + mt * 16 + g + half * 8;
                float v0 = c[mt][nt][half * 2 + 0] + bias[col];
                float v1 = c[mt][nt][half * 2 + 1] + bias[col + 1];
                if (sel == 0) {
                    g_q[(size_t)m * EMB + col]     = v0 * QSCALE;
                    g_q[(size_t)m * EMB + col + 1] = v1 * QSCALE;
                } else {
                    float* dst = (sel == 1) ? g_k : g_v;
                    dst[(size_t)m * EMB + col]     = v0;
                    dst[(size_t)m * EMB + col + 1] = v1;
                    if (write_cache) {
                        int bidx = m >> 9, t = m & 511;
                        float* cd = (sel == 1) ? okc : ovc;
                        size_t o = ((size_t)bidx * KVLEN + KVOLD + t) * EMB + col;
                        cd[o] = v0; cd[o + 1] = v1;
                    }
                }
            }
        }
    }
}

/* Output projection: out = g_attn @ wo^T + bo. grid (16,16) */
__global__ void __launch_bounds__(256, 2) proj_kernel(
    const float* __restrict__ wo, const float* __restrict__ bo,
    float* __restrict__ out)
{
    extern __shared__ float gsm[];
    float* As = gsm;
    float* Bs = gsm + 3 * GST;

    const int tid  = threadIdx.x;
    const int lane = tid & 31, wid = tid >> 5;
    const int g = lane >> 2, tg = lane & 3;
    const int wm = wid >> 2, wn = wid & 3;
    const int nblk = blockIdx.x, mb = blockIdx.y;

    float c[4][4][4] = {};
    gemm_main(g_attn + (size_t)(mb * 128) * EMB, wo + (size_t)(nblk * 128) * EMB,
              c, As, Bs, tid);

    #pragma unroll
    for (int mt = 0; mt < 4; mt++)
        #pragma unroll
        for (int nt = 0; nt < 4; nt++) {
            int col = nblk * 128 + wn * 32 + nt * 8 + 2 * tg;
            #pragma unroll
            for (int half = 0; half < 2; half++) {
                int m = mb * 128 + wm * 64 + mt * 16 + g + half * 8;
                out[(size_t)m * EMB + col]     = c[mt][nt][half * 2 + 0] + bo[col];
                out[(size_t)m * EMB + col + 1] = c[mt][nt][half * 2 + 1] + bo[col + 1];
            }
        }
}

/* ================================================================== */
/* Flash attention. Q tile 128, KV tile 64. 512 thr = 16 warps        */
/* (8 wm x 2 wn). S warp-tile m16n32; PV warp-tile m16n64.            */
/* K: 2-stage cp.async (raw f32, cvt at frag). V: reg-prefetch LDG,   */
/* cvt+STS transposed. Softmax: named 64-thread pair barriers.        */
/* ================================================================== */
#define LQ 132   /* Qs stride (tf32)  */
#define LK 132   /* Kb stride (f32)   */
#define LV 69    /* Vs stride (tf32, d-major) */
#define LP 68    /* Ps stride (tf32)  */
#define OFF_KB 16896                   /* 128*132 */
#define OFF_VS (OFF_KB + 2 * 64 * LK)  /* + 16896 */
#define OFF_PS (OFF_VS + 128 * LV)     /* + 8832  */
#define ATT_SMEM ((OFF_PS + 128 * LP) * 4)   /* 205312 B */

__global__ void __launch_bounds__(512, 1) attn_kernel(
    const float* __restrict__ kc_in, const float* __restrict__ vc_in,
    const float* __restrict__ mask)
{
    extern __shared__ unsigned smu[];
    unsigned* Qs = smu;
    float*    Kb = (float*)(smu + OFF_KB);
    unsigned* Vs = smu + OFF_VS;
    unsigned* Ps = smu + OFF_PS;
    __shared__ float pmax[2][128], psum[2][128];

    const int tid  = threadIdx.x;
    const int lane = tid & 31, wid = tid >> 5;
    const int g = lane >> 2, tg = lane & 3;
    const int wm = wid >> 1, wn = wid & 1;
    const int qt = blockIdx.x, h = blockIdx.y, b = blockIdx.z;

    const int r0 = wm * 16 + g;
    const int r1 = r0 + 8;
    const int cb = wn * 32;

    const float* kold = kc_in + (size_t)b * KVLEN * EMB + h * HD;
    const float* vold = vc_in + (size_t)b * KVLEN * EMB + h * HD;
    const float* knew = g_k + (size_t)b * TGT * EMB + h * HD;
    const float* vnew = g_v + (size_t)b * TGT * EMB + h * HD;
    const float* mbase = mask + (size_t)(qt * 128) * KVLEN;

    /* prime cp.async K(0) */
    {
        #pragma unroll
        for (int p = 0; p < 4; p++) {
            int cc = tid + p * 512;
            int j = cc >> 5, ch = (cc & 31) << 2;
            cp16(sm_u32(Kb + j * LK + ch), kold + (size_t)j * EMB + ch);
        }
        CP_COMMIT();
    }

    /* load Q (tf32) */
    #pragma unroll
    for (int t = 0; t < 8; t++) {
        int idx = tid + t * 512;
        int row = idx >> 5, d4 = (idx & 31) << 2;
        float4 v = *(const float4*)(g_q + (size_t)(b * TGT + qt * 128 + row) * EMB + h * HD + d4);
        Qs[row * LQ + d4 + 0] = f2tf(v.x); Qs[row * LQ + d4 + 1] = f2tf(v.y);
        Qs[row * LQ + d4 + 2] = f2tf(v.z); Qs[row * LQ + d4 + 3] = f2tf(v.w);
    }

    /* prime V(0) into registers */
    float4 vreg[4];
    #pragma unroll
    for (int p = 0; p < 4; p++) {
        int idx = tid + p * 512;
        int j = idx >> 5, d4 = (idx & 31) << 2;
        vreg[p] = *(const float4*)(vold + (size_t)j * EMB + d4);
    }

    float m0 = -1e30f, m1 = -1e30f, l0 = 0.f, l1 = 0.f;
    float o[8][4] = {};
    int cur = 0;

    for (int t = 0; t < KVLEN / 64; t++) {
        const int kt0 = t * 64;

        /* issue cp.async K(t+1) */
        if (t < KVLEN / 64 - 1) {
            int nk = kt0 + 64;
            const float* ksrc = (nk < KVOLD) ? kold + (size_t)nk * EMB
                                             : knew + (size_t)(nk - KVOLD) * EMB;
            float* kdst = Kb + (cur ^ 1) * 64 * LK;
            #pragma unroll
            for (int p = 0; p < 4; p++) {
                int cc = tid + p * 512;
                int j = cc >> 5, ch = (cc & 31) << 2;
                cp16(sm_u32(kdst + j * LK + ch), ksrc + (size_t)j * EMB + ch);
            }
            CP_COMMIT();
        }

        /* V(t): cvt + transposed STS */
        #pragma unroll
        for (int p = 0; p < 4; p++) {
            int idx = tid + p * 512;
            int j = idx >> 5, d4 = (idx & 31) << 2;
            Vs[(d4 + 0) * LV + j] = f2tf(vreg[p].x);
            Vs[(d4 + 1) * LV + j] = f2tf(vreg[p].y);
            Vs[(d4 + 2) * LV + j] = f2tf(vreg[p].z);
            Vs[(d4 + 3) * LV + j] = f2tf(vreg[p].w);
        }

        /* mask prefetch */
        float2 mA[4], mB[4];
        #pragma unroll
        for (int nt = 0; nt < 4; nt++) {
            int col = cb + nt * 8 + 2 * tg;
            mA[nt] = *(const float2*)(mbase + (size_t)r0 * KVLEN + kt0 + col);
            mB[nt] = *(const float2*)(mbase + (size_t)r1 * KVLEN + kt0 + col);
        }

        if (t < KVLEN / 64 - 1) CP_WAIT(1); else CP_WAIT(0);
        __syncthreads();             /* K(t) + V(t) visible; prev tile fully consumed */

        /* S = Q K^T */
        const float* Kf = Kb + cur * 64 * LK;
        float s[4][4] = {};
        #pragma unroll
        for (int ks = 0; ks < 16; ks++) {
            int k0 = ks * 8 + tg;
            unsigned a[4] = { Qs[r0 * LQ + k0], Qs[r1 * LQ + k0],
                              Qs[r0 * LQ + k0 + 4], Qs[r1 * LQ + k0 + 4] };
            #pragma unroll
            for (int nt = 0; nt < 4; nt++) {
                int n = cb + nt * 8 + g;
                unsigned bb[2] = { f2tf(Kf[n * LK + k0]), f2tf(Kf[n * LK + k0 + 4]) };
                mma_tf32(s[nt], a, bb);
            }
        }

        /* + mask */
        #pragma unroll
        for (int nt = 0; nt < 4; nt++) {
            s[nt][0] += mA[nt].x; s[nt][1] += mA[nt].y;
            s[nt][2] += mB[nt].x; s[nt][3] += mB[nt].y;
        }

        /* row max over this warp's 32 cols (quad reduce) */
        float mx0 = -1e30f, mx1 = -1e30f;
        #pragma unroll
        for (int nt = 0; nt < 4; nt++) {
            mx0 = fmaxf(mx0, fmaxf(s[nt][0], s[nt][1]));
            mx1 = fmaxf(mx1, fmaxf(s[nt][2], s[nt][3]));
        }
        mx0 = fmaxf(mx0, __shfl_xor_sync(0xffffffffu, mx0, 1));
        mx0 = fmaxf(mx0, __shfl_xor_sync(0xffffffffu, mx0, 2));
        mx1 = fmaxf(mx1, __shfl_xor_sync(0xffffffffu, mx1, 1));
        mx1 = fmaxf(mx1, __shfl_xor_sync(0xffffffffu, mx1, 2));
        if (tg == 0) { pmax[wn][r0] = mx0; pmax[wn][r1] = mx1; }
        BAR_PAIR(1 + wm);

        float mn0 = fmaxf(m0, fmaxf(pmax[0][r0], pmax[1][r0]));
        float mn1 = fmaxf(m1, fmaxf(pmax[0][r1], pmax[1][r1]));
        float s0s = 0.f, s1s = 0.f;
        #pragma unroll
        for (int nt = 0; nt < 4; nt++) {
            s[nt][0] = __expf(s[nt][0] - mn0);
            s[nt][1] = __expf(s[nt][1] - mn0);
            s[nt][2] = __expf(s[nt][2] - mn1);
            s[nt][3] = __expf(s[nt][3] - mn1);
            s0s += s[nt][0] + s[nt][1];
            s1s += s[nt][2] + s[nt][3];
            int col = cb + nt * 8 + 2 * tg;
            Ps[r0 * LP + col]     = f2tf(s[nt][0]);
            Ps[r0 * LP + col + 1] = f2tf(s[nt][1]);
            Ps[r1 * LP + col]     = f2tf(s[nt][2]);
            Ps[r1 * LP + col + 1] = f2tf(s[nt][3]);
        }
        s0s += __shfl_xor_sync(0xffffffffu, s0s, 1);
        s0s += __shfl_xor_sync(0xffffffffu, s0s, 2);
        s1s += __shfl_xor_sync(0xffffffffu, s1s, 1);
        s1s += __shfl_xor_sync(0xffffffffu, s1s, 2);
        if (tg == 0) { psum[wn][r0] = s0s; psum[wn][r1] = s1s; }
        BAR_PAIR(1 + wm);

        float sc0 = __expf(m0 - mn0), sc1 = __expf(m1 - mn1);
        l0 = l0 * sc0 + psum[0][r0] + psum[1][r0];
        l1 = l1 * sc1 + psum[0][r1] + psum[1][r1];
        m0 = mn0; m1 = mn1;
        #pragma unroll
        for (int nt = 0; nt < 8; nt++) {
            o[nt][0] *= sc0; o[nt][1] *= sc0;
            o[nt][2] *= sc1; o[nt][3] *= sc1;
        }

        /* prefetch V(t+1) into regs (latency hidden behind PV) */
        if (t < KVLEN / 64 - 1) {
            int nk = kt0 + 64;
            const float* vsrc = (nk < KVOLD) ? vold + (size_t)nk * EMB
                                             : vnew + (size_t)(nk - KVOLD) * EMB;
            #pragma unroll
            for (int p = 0; p < 4; p++) {
                int idx = tid + p * 512;
                int j = idx >> 5, d4 = (idx & 31) << 2;
                vreg[p] = *(const float4*)(vsrc + (size_t)j * EMB + d4);
            }
        }

        /* O += P V */
        #pragma unroll
        for (int ks = 0; ks < 8; ks++) {
            int k0 = ks * 8 + tg;
            unsigned a[4] = { Ps[r0 * LP + k0], Ps[r1 * LP + k0],
                              Ps[r0 * LP + k0 + 4], Ps[r1 * LP + k0 + 4] };
            #pragma unroll
            for (int nt = 0; nt < 8; nt++) {
                int n = wn * 64 + nt * 8 + g;
                unsigned bb[2] = { Vs[n * LV + k0], Vs[n * LV + k0 + 4] };
                mma_tf32(o[nt], a, bb);
            }
        }
        __syncthreads();             /* protect Vs/Ps/Kb[cur] before next tile writes */
        cur ^= 1;
    }

    /* normalize + write */
    float inv0 = 1.f / l0, inv1 = 1.f / l1;
    int row0 = b * TGT + qt * 128 + r0;
    int row1 = b * TGT + qt * 128 + r1;
    #pragma unroll
    for (int nt = 0; nt < 8; nt++) {
        int col = wn * 64 + nt * 8 + 2 * tg;
        g_attn[(size_t)row0 * EMB + h * HD + col]     = o[nt][0] * inv0;
        g_attn[(size_t)row0 * EMB + h * HD + col + 1] = o[nt][1] * inv0;
        g_attn[(size_t)row1 * EMB + h * HD + col]     = o[nt][2] * inv1;
        g_attn[(size_t)row1 * EMB + h * HD + col + 1] = o[nt][3] * inv1;
    }
}

/* ------------------------------------------------------------------ */
extern "C" void kernel_launch(void* const* d_in, const int* in_sizes, int n_in,
                              void* d_out, int out_size)
{
    const float* x       = (const float*)d_in[0];
    const float* k_cache = (const float*)d_in[1];
    const float* v_cache = (const float*)d_in[2];
    const float* mask    = (const float*)d_in[3];
    const float* wq = (const float*)d_in[4];
    const float* bq = (const float*)d_in[5];
    const float* wk = (const float*)d_in[6];
    const float* bk = (const float*)d_in[7];
    const float* wv = (const float*)d_in[8];
    const float* bv = (const float*)d_in[9];
    const float* wo = (const float*)d_in[10];
    const float* bo = (const float*)d_in[11];

    float* out = (float*)d_out;
    long long need = (long long)MROWS * EMB + 2LL * BSZ * KVLEN * EMB;
    int write_cache = ((long long)out_size >= need) ? 1 : 0;
    float* okc = out + (size_t)MROWS * EMB;
    float* ovc = okc + (size_t)BSZ * KVLEN * EMB;

    cudaFuncSetAttribute(attn_kernel,
                         cudaFuncAttributeMaxDynamicSharedMemorySize, ATT_SMEM);
    cudaFuncSetAttribute(qkv_kernel,
                         cudaFuncAttributeMaxDynamicSharedMemorySize, GEMM_SMEM);
    cudaFuncSetAttribute(proj_kernel,
                         cudaFuncAttributeMaxDynamicSharedMemorySize, GEMM_SMEM);

    if (write_cache) {
        size_t bytes = (size_t)KVOLD * EMB * sizeof(float);
        for (int bb = 0; bb < BSZ; bb++) {
            cudaMemcpyAsync(okc + (size_t)bb * KVLEN * EMB,
                            k_cache + (size_t)bb * KVLEN * EMB,
                            bytes, cudaMemcpyDeviceToDevice, 0);
            cudaMemcpyAsync(ovc + (size_t)bb * KVLEN * EMB,
                            v_cache + (size_t)bb * KVLEN * EMB,
                            bytes, cudaMemcpyDeviceToDevice, 0);
        }
    }

    qkv_kernel<<<dim3(48, 16), 256, GEMM_SMEM>>>(x, wq, bq, wk, bk, wv, bv,
                                                 okc, ovc, write_cache);
    attn_kernel<<<dim3(4, 16, 4), 512, ATT_SMEM>>>(k_cache, v_cache, mask);
    proj_kernel<<<dim3(16, 16), 256, GEMM_SMEM>>>(wo, bo, out);
}

// round 5
// speedup vs baseline: 3.2660x; 1.1019x over previous
#include <cuda_runtime.h>

#define BSZ   4
#define TGT   512
#define KVLEN 4096
#define KVOLD (KVLEN - TGT)   /* 3584 */
#define EMB   2048
#define NH    16
#define HD    128
#define MROWS (BSZ * TGT)     /* 2048 */
#define SLOT  (EMB * EMB)     /* 4M u32 per matrix */
#define QSCALE 0.08838834764831845f  /* 128^-0.5 */

/* scratch (static device arrays: allocation-free per harness rules) */
__device__ float g_q[MROWS * EMB];
__device__ float g_k[MROWS * EMB];
__device__ float g_v[MROWS * EMB];
__device__ float g_attn[MROWS * EMB];
/* permuted tf32 operands: 0=x(A) 1=wq(B) 2=wk(B) 3=wv(B) 4=wo(B) 5=attn(A) */
__device__ unsigned g_p[6 * SLOT];

/* ---------------- helpers ---------------- */
__device__ __forceinline__ unsigned f2tf(float f) {
    unsigned u;
    asm("cvt.rna.tf32.f32 %0, %1;" : "=r"(u) : "f"(f));
    return u;
}
__device__ __forceinline__ void mma4(float c[4], const uint4& a, unsigned b0, unsigned b1) {
    asm("mma.sync.aligned.m16n8k8.row.col.f32.tf32.tf32.f32 "
        "{%0,%1,%2,%3},{%4,%5,%6,%7},{%8,%9},{%0,%1,%2,%3};"
        : "+f"(c[0]), "+f"(c[1]), "+f"(c[2]), "+f"(c[3])
        : "r"(a.x), "r"(a.y), "r"(a.z), "r"(a.w), "r"(b0), "r"(b1));
}
__device__ __forceinline__ unsigned sm_u32(const void* p) {
    return (unsigned)__cvta_generic_to_shared(p);
}
__device__ __forceinline__ void cp16(unsigned dst, const void* src) {
    asm volatile("cp.async.cg.shared.global [%0], [%1], 16;" :: "r"(dst), "l"(src));
}
#define CP_COMMIT() asm volatile("cp.async.commit_group;")
#define CP_WAIT(n)  asm volatile("cp.async.wait_group %0;" :: "n"(n))
#define BAR_PAIR(id) asm volatile("bar.sync %0, 64;" :: "r"(id) : "memory")

/* ---------------- permute/convert kernels ----------------
   Fragment layout per matrix (2048x2048 row-major src):
   dst_uint4[(MI*256 + KSL)*32 + lane], MI = row/16, KSL = col/8,
   lane = g*4+tg (g=0..7, tg=0..3).
   A-type: {src[r][c], src[r+8][c], src[r][c+4], src[r+8][c+4]}
   B-type: {src[r][c], src[r][c+4], src[r+8][c], src[r+8][c+4]}
   with r = 16*MI+g, c = 8*KSL+tg. All values tf32-rounded.       */
__device__ __forceinline__ void permute_one(const float* __restrict__ src,
                                            uint4* __restrict__ dst,
                                            unsigned gid, int btype)
{
    unsigned lane = gid & 31, KSL = (gid >> 5) & 255, MI = gid >> 13;
    unsigned g = lane >> 2, tg = lane & 3;
    const float* p = src + (size_t)(MI * 16 + g) * EMB + KSL * 8 + tg;
    float v0 = p[0], v1 = p[8 * EMB], v2 = p[4], v3 = p[8 * EMB + 4];
    uint4 u;
    if (btype) { u.x = f2tf(v0); u.y = f2tf(v2); u.z = f2tf(v1); u.w = f2tf(v3); }
    else       { u.x = f2tf(v0); u.y = f2tf(v1); u.z = f2tf(v2); u.w = f2tf(v3); }
    dst[gid] = u;
}

__global__ void __launch_bounds__(256) convert5_kernel(
    const float* __restrict__ x,  const float* __restrict__ wq,
    const float* __restrict__ wk, const float* __restrict__ wv,
    const float* __restrict__ wo)
{
    int slot = blockIdx.y;
    const float* src = (slot == 0) ? x : (slot == 1) ? wq :
                       (slot == 2) ? wk : (slot == 3) ? wv : wo;
    unsigned gid = blockIdx.x * 256 + threadIdx.x;
    permute_one(src, (uint4*)(g_p + (size_t)slot * SLOT), gid, slot != 0);
}

__global__ void __launch_bounds__(256) convert_attn_kernel()
{
    unsigned gid = blockIdx.x * 256 + threadIdx.x;
    permute_one(g_attn, (uint4*)(g_p + 5 * (size_t)SLOT), gid, 0);
}

/* ---------------- dense GEMM: C[128,128] = A @ B^T, pre-permuted tf32 ----
   block 256 thr (8 warps, wm2 x wn4), k-tile 32 (4 slices), 3-stage cp.async.
   stage = A 1024 uint4 + B 1024 uint4 = 32KB; 3 stages = 96KB.            */
#define GSTG 2048   /* uint4 per stage */
#define GEMM_SMEM (3 * GSTG * 16)

__device__ __forceinline__ void gemm_main(
    const uint4* __restrict__ Ag,   /* + mb*8*8192 pre-applied */
    const uint4* __restrict__ Bg,   /* + nblk*8*8192 pre-applied */
    float c[4][4][4], uint4* S, int tid)
{
    const int lane = tid & 31, wid = tid >> 5;
    const int wm = wid >> 2, wn = wid & 3;

    /* prime stages 0,1 */
    for (int st = 0; st < 2; st++) {
        for (int i = 0; i < 8; i++) {
            int ch = tid + i * 256;
            int half = ch >> 10, cc = ch & 1023;
            int mi = cc >> 7, rest = cc & 127;
            const uint4* src = (half ? Bg : Ag) + (size_t)mi * 8192 + st * 128 + rest;
            cp16(sm_u32(S + st * GSTG + half * 1024 + cc), src);
        }
        CP_COMMIT();
    }

    for (int kt = 0; kt < 64; kt++) {
        if (kt < 63) CP_WAIT(1); else CP_WAIT(0);
        __syncthreads();

        if (kt + 2 < 64) {
            int st = (kt + 2) % 3;
            for (int i = 0; i < 8; i++) {
                int ch = tid + i * 256;
                int half = ch >> 10, cc = ch & 1023;
                int mi = cc >> 7, rest = cc & 127;
                const uint4* src = (half ? Bg : Ag) + (size_t)mi * 8192 + (kt + 2) * 128 + rest;
                cp16(sm_u32(S + st * GSTG + half * 1024 + cc), src);
            }
            CP_COMMIT();
        }

        const uint4* Af = S + (kt % 3) * GSTG;
        const uint4* Bf = Af + 1024;
        #pragma unroll
        for (int ks = 0; ks < 4; ks++) {
            uint4 a[4], bu[2];
            #pragma unroll
            for (int mt = 0; mt < 4; mt++)
                a[mt] = Af[((wm * 4 + mt) * 4 + ks) * 32 + lane];
            #pragma unroll
            for (int p = 0; p < 2; p++)
                bu[p] = Bf[((wn * 2 + p) * 4 + ks) * 32 + lane];
            #pragma unroll
            for (int mt = 0; mt < 4; mt++) {
                mma4(c[mt][0], a[mt], bu[0].x, bu[0].y);
                mma4(c[mt][1], a[mt], bu[0].z, bu[0].w);
                mma4(c[mt][2], a[mt], bu[1].x, bu[1].y);
                mma4(c[mt][3], a[mt], bu[1].z, bu[1].w);
            }
        }
    }
}

/* Fused QKV: grid (48,16): sel = nb>>4, nblk = nb&15 */
__global__ void __launch_bounds__(256, 2) qkv_kernel(
    const float* __restrict__ bq, const float* __restrict__ bk,
    const float* __restrict__ bv,
    float* __restrict__ okc, float* __restrict__ ovc, int write_cache)
{
    extern __shared__ uint4 S[];
    const int tid = threadIdx.x;
    const int lane = tid & 31, wid = tid >> 5;
    const int g = lane >> 2, tg = lane & 3;
    const int wm = wid >> 2, wn = wid & 3;
    const int nb = blockIdx.x, mb = blockIdx.y;
    const int sel = nb >> 4, nblk = nb & 15;
    const float* bias = (sel == 0) ? bq : (sel == 1) ? bk : bv;

    const uint4* Ag = (const uint4*)(g_p) + (size_t)(mb * 8) * 8192;
    const uint4* Bg = (const uint4*)(g_p + (size_t)(1 + sel) * SLOT) + (size_t)(nblk * 8) * 8192;

    float c[4][4][4] = {};
    gemm_main(Ag, Bg, c, S, tid);

    #pragma unroll
    for (int mt = 0; mt < 4; mt++) {
        #pragma unroll
        for (int nt = 0; nt < 4; nt++) {
            int col = nblk * 128 + wn * 32 + nt * 8 + 2 * tg;
            #pragma unroll
            for (int half = 0; half < 2; half++) {
                int m = mb * 128 + wm * 64 + mt * 16 + g + half * 8;
                float v0 = c[mt][nt][half * 2 + 0] + bias[col];
                float v1 = c[mt][nt][half * 2 + 1] + bias[col + 1];
                if (sel == 0) {
                    g_q[(size_t)m * EMB + col]     = v0 * QSCALE;
                    g_q[(size_t)m * EMB + col + 1] = v1 * QSCALE;
                } else {
                    float* dst = (sel == 1) ? g_k : g_v;
                    dst[(size_t)m * EMB + col]     = v0;
                    dst[(size_t)m * EMB + col + 1] = v1;
                    if (write_cache) {
                        int bidx = m >> 9, t = m & 511;
                        float* cd = (sel == 1) ? okc : ovc;
                        size_t o = ((size_t)bidx * KVLEN + KVOLD + t) * EMB + col;
                        cd[o] = v0; cd[o + 1] = v1;
                    }
                }
            }
        }
    }
}

/* Output projection: grid (16,16) */
__global__ void __launch_bounds__(256, 2) proj_kernel(
    const float* __restrict__ bo, float* __restrict__ out)
{
    extern __shared__ uint4 S[];
    const int tid = threadIdx.x;
    const int lane = tid & 31, wid = tid >> 5;
    const int g = lane >> 2, tg = lane & 3;
    const int wm = wid >> 2, wn = wid & 3;
    const int nblk = blockIdx.x, mb = blockIdx.y;

    const uint4* Ag = (const uint4*)(g_p + 5 * (size_t)SLOT) + (size_t)(mb * 8) * 8192;
    const uint4* Bg = (const uint4*)(g_p + 4 * (size_t)SLOT) + (size_t)(nblk * 8) * 8192;

    float c[4][4][4] = {};
    gemm_main(Ag, Bg, c, S, tid);

    #pragma unroll
    for (int mt = 0; mt < 4; mt++)
        #pragma unroll
        for (int nt = 0; nt < 4; nt++) {
            int col = nblk * 128 + wn * 32 + nt * 8 + 2 * tg;
            #pragma unroll
            for (int half = 0; half < 2; half++) {
                int m = mb * 128 + wm * 64 + mt * 16 + g + half * 8;
                out[(size_t)m * EMB + col]     = c[mt][nt][half * 2 + 0] + bo[col];
                out[(size_t)m * EMB + col + 1] = c[mt][nt][half * 2 + 1] + bo[col + 1];
            }
        }
}

/* ---------------- flash attention, fully-permuted fragments ----------------
   512 thr, 16 warps (wm8 x wn2). Q tile 128 rows, KV tile 64.
   smem (uint4): Qp[128 grp][32]  Kp[64 grp][32]  Vp[64 grp][32]  Pp[64 grp][32]
   = 4096 + 2048*3 = 10240 uint4 = 160KB dynamic.                            */
#define OQ 0
#define OK 4096
#define OV 6144
#define OP 8192
#define ATT_SMEM (10240 * 16)

__global__ void __launch_bounds__(512, 1) attn_kernel(
    const float* __restrict__ kc_in, const float* __restrict__ vc_in,
    const float* __restrict__ mask)
{
    extern __shared__ uint4 smq[];
    uint4* Qp = smq + OQ;
    uint4* Kp = smq + OK;
    uint4* Vp = smq + OV;
    uint4* Pp = smq + OP;
    __shared__ float pmax[2][128], psum[2][128];

    const int tid  = threadIdx.x;
    const int lane = tid & 31, wid = tid >> 5;
    const int g = lane >> 2, tg = lane & 3;
    const int wm = wid >> 1, wn = wid & 1;
    const int qt = blockIdx.x, h = blockIdx.y, b = blockIdx.z;

    const int r0 = wm * 16 + g;
    const int r1 = r0 + 8;
    const int cb = wn * 32;

    const float* kold = kc_in + (size_t)b * KVLEN * EMB + h * HD;
    const float* vold = vc_in + (size_t)b * KVLEN * EMB + h * HD;
    const float* knew = g_k + (size_t)b * TGT * EMB + h * HD;
    const float* vnew = g_v + (size_t)b * TGT * EMB + h * HD;
    const float* mbase = mask + (size_t)(qt * 128) * KVLEN;

    /* load + permute Q (A-type): 128 grps, warp w owns grps w*8..w*8+7 */
    {
        const float* qb = g_q + (size_t)(b * TGT + qt * 128) * EMB + h * HD;
        #pragma unroll
        for (int q = 0; q < 8; q++) {
            int G = wid * 8 + q;
            int mi = G >> 4, ksl = G & 15;
            const float* p = qb + (size_t)(mi * 16 + g) * EMB + ksl * 8 + tg;
            uint4 u;
            u.x = f2tf(p[0]); u.y = f2tf(p[8 * EMB]);
            u.z = f2tf(p[4]); u.w = f2tf(p[8 * EMB + 4]);
            Qp[G * 32 + lane] = u;
        }
    }

    /* prefetch K(0)/V(0) into registers.
       K (B-type over [j64][d128]): grp = pi(j/16)*16 + ksl(d/8); warp owns 4 grps.
       V (B-type over [d128][j64]): grp = pi(d/16)*8 + ksl(j/8).               */
    float kreg[4][4], vreg[4][4];
    {
        #pragma unroll
        for (int q = 0; q < 4; q++) {
            int G = wid * 4 + q;
            { int pi = G >> 4, ksl = G & 15;
              const float* p = kold + (size_t)(pi * 16 + g) * EMB + ksl * 8 + tg;
              kreg[q][0] = p[0]; kreg[q][1] = p[4];
              kreg[q][2] = p[8 * EMB]; kreg[q][3] = p[8 * EMB + 4]; }
            { int pi = G >> 3, ksl = G & 7;
              const float* p = vold + (size_t)(ksl * 8 + tg) * EMB + pi * 16 + g;
              vreg[q][0] = p[0]; vreg[q][1] = p[4 * EMB];
              vreg[q][2] = p[8]; vreg[q][3] = p[4 * EMB + 8]; }
        }
    }

    float m0 = -1e30f, m1 = -1e30f, l0 = 0.f, l1 = 0.f;
    float o[8][4] = {};

    for (int t = 0; t < KVLEN / 64; t++) {
        const int kt0 = t * 64;

        /* STS K(t), V(t) permuted */
        #pragma unroll
        for (int q = 0; q < 4; q++) {
            int G = wid * 4 + q;
            uint4 uk, uv;
            uk.x = f2tf(kreg[q][0]); uk.y = f2tf(kreg[q][1]);
            uk.z = f2tf(kreg[q][2]); uk.w = f2tf(kreg[q][3]);
            uv.x = f2tf(vreg[q][0]); uv.y = f2tf(vreg[q][1]);
            uv.z = f2tf(vreg[q][2]); uv.w = f2tf(vreg[q][3]);
            Kp[G * 32 + lane] = uk;
            Vp[G * 32 + lane] = uv;
        }

        /* mask prefetch */
        float2 mA[4], mB[4];
        #pragma unroll
        for (int nt = 0; nt < 4; nt++) {
            int col = cb + nt * 8 + 2 * tg;
            mA[nt] = *(const float2*)(mbase + (size_t)r0 * KVLEN + kt0 + col);
            mB[nt] = *(const float2*)(mbase + (size_t)r1 * KVLEN + kt0 + col);
        }
        __syncthreads();

        /* S = Q K^T : per slice 1 a-LDS.128 + 2 b-LDS.128 + 4 HMMA */
        float s[4][4] = {};
        #pragma unroll
        for (int ks = 0; ks < 16; ks++) {
            uint4 a  = Qp[(wm * 16 + ks) * 32 + lane];
            uint4 b0 = Kp[((2 * wn) * 16 + ks) * 32 + lane];
            uint4 b1 = Kp[((2 * wn + 1) * 16 + ks) * 32 + lane];
            mma4(s[0], a, b0.x, b0.y);
            mma4(s[1], a, b0.z, b0.w);
            mma4(s[2], a, b1.x, b1.y);
            mma4(s[3], a, b1.z, b1.w);
        }

        #pragma unroll
        for (int nt = 0; nt < 4; nt++) {
            s[nt][0] += mA[nt].x; s[nt][1] += mA[nt].y;
            s[nt][2] += mB[nt].x; s[nt][3] += mB[nt].y;
        }

        /* row max (quad reduce) */
        float mx0 = -1e30f, mx1 = -1e30f;
        #pragma unroll
        for (int nt = 0; nt < 4; nt++) {
            mx0 = fmaxf(mx0, fmaxf(s[nt][0], s[nt][1]));
            mx1 = fmaxf(mx1, fmaxf(s[nt][2], s[nt][3]));
        }
        mx0 = fmaxf(mx0, __shfl_xor_sync(0xffffffffu, mx0, 1));
        mx0 = fmaxf(mx0, __shfl_xor_sync(0xffffffffu, mx0, 2));
        mx1 = fmaxf(mx1, __shfl_xor_sync(0xffffffffu, mx1, 1));
        mx1 = fmaxf(mx1, __shfl_xor_sync(0xffffffffu, mx1, 2));
        if (tg == 0) { pmax[wn][r0] = mx0; pmax[wn][r1] = mx1; }
        BAR_PAIR(1 + wm);

        float mn0 = fmaxf(m0, fmaxf(pmax[0][r0], pmax[1][r0]));
        float mn1 = fmaxf(m1, fmaxf(pmax[0][r1], pmax[1][r1]));
        float s0s = 0.f, s1s = 0.f;
        /* P STS permuted (A-type over [q-rows][j]): grp = wm*8 + (cb+nt*8)/8 */
        unsigned* Pu = (unsigned*)Pp;
        const int pbase = (wm * 8 + wn * 4) * 128;
        const int eoff = (g * 4 + (tg & 1) * 2) * 4 + (tg >> 1) * 2;
        #pragma unroll
        for (int nt = 0; nt < 4; nt++) {
            s[nt][0] = __expf(s[nt][0] - mn0);
            s[nt][1] = __expf(s[nt][1] - mn0);
            s[nt][2] = __expf(s[nt][2] - mn1);
            s[nt][3] = __expf(s[nt][3] - mn1);
            s0s += s[nt][0] + s[nt][1];
            s1s += s[nt][2] + s[nt][3];
            int bb = pbase + nt * 128 + eoff;
            Pu[bb + 0] = f2tf(s[nt][0]);
            Pu[bb + 4] = f2tf(s[nt][1]);
            Pu[bb + 1] = f2tf(s[nt][2]);
            Pu[bb + 5] = f2tf(s[nt][3]);
        }
        s0s += __shfl_xor_sync(0xffffffffu, s0s, 1);
        s0s += __shfl_xor_sync(0xffffffffu, s0s, 2);
        s1s += __shfl_xor_sync(0xffffffffu, s1s, 1);
        s1s += __shfl_xor_sync(0xffffffffu, s1s, 2);
        if (tg == 0) { psum[wn][r0] = s0s; psum[wn][r1] = s1s; }
        BAR_PAIR(1 + wm);

        float sc0 = __expf(m0 - mn0), sc1 = __expf(m1 - mn1);
        l0 = l0 * sc0 + psum[0][r0] + psum[1][r0];
        l1 = l1 * sc1 + psum[0][r1] + psum[1][r1];
        m0 = mn0; m1 = mn1;
        #pragma unroll
        for (int nt = 0; nt < 8; nt++) {
            o[nt][0] *= sc0; o[nt][1] *= sc0;
            o[nt][2] *= sc1; o[nt][3] *= sc1;
        }

        /* prefetch K/V(t+1) */
        if (t < KVLEN / 64 - 1) {
            int nk = kt0 + 64;
            const float* ks_ = (nk < KVOLD) ? kold + (size_t)nk * EMB
                                            : knew + (size_t)(nk - KVOLD) * EMB;
            const float* vs_ = (nk < KVOLD) ? vold + (size_t)nk * EMB
                                            : vnew + (size_t)(nk - KVOLD) * EMB;
            #pragma unroll
            for (int q = 0; q < 4; q++) {
                int G = wid * 4 + q;
                { int pi = G >> 4, ksl = G & 15;
                  const float* p = ks_ + (size_t)(pi * 16 + g) * EMB + ksl * 8 + tg;
                  kreg[q][0] = p[0]; kreg[q][1] = p[4];
                  kreg[q][2] = p[8 * EMB]; kreg[q][3] = p[8 * EMB + 4]; }
                { int pi = G >> 3, ksl = G & 7;
                  const float* p = vs_ + (size_t)(ksl * 8 + tg) * EMB + pi * 16 + g;
                  vreg[q][0] = p[0]; vreg[q][1] = p[4 * EMB];
                  vreg[q][2] = p[8]; vreg[q][3] = p[4 * EMB + 8]; }
            }
        }

        /* O += P V : per slice 1 a-LDS.128 + 4 b-LDS.128 + 8 HMMA */
        #pragma unroll
        for (int ks = 0; ks < 8; ks++) {
            uint4 a  = Pp[(wm * 8 + ks) * 32 + lane];
            uint4 v0 = Vp[((4 * wn + 0) * 8 + ks) * 32 + lane];
            uint4 v1 = Vp[((4 * wn + 1) * 8 + ks) * 32 + lane];
            uint4 v2 = Vp[((4 * wn + 2) * 8 + ks) * 32 + lane];
            uint4 v3 = Vp[((4 * wn + 3) * 8 + ks) * 32 + lane];
            mma4(o[0], a, v0.x, v0.y);
            mma4(o[1], a, v0.z, v0.w);
            mma4(o[2], a, v1.x, v1.y);
            mma4(o[3], a, v1.z, v1.w);
            mma4(o[4], a, v2.x, v2.y);
            mma4(o[5], a, v2.z, v2.w);
            mma4(o[6], a, v3.x, v3.y);
            mma4(o[7], a, v3.z, v3.w);
        }
        __syncthreads();
    }

    /* normalize + write */
    float inv0 = 1.f / l0, inv1 = 1.f / l1;
    int row0 = b * TGT + qt * 128 + r0;
    int row1 = b * TGT + qt * 128 + r1;
    #pragma unroll
    for (int nt = 0; nt < 8; nt++) {
        int col = wn * 64 + nt * 8 + 2 * tg;
        g_attn[(size_t)row0 * EMB + h * HD + col]     = o[nt][0] * inv0;
        g_attn[(size_t)row0 * EMB + h * HD + col + 1] = o[nt][1] * inv0;
        g_attn[(size_t)row1 * EMB + h * HD + col]     = o[nt][2] * inv1;
        g_attn[(size_t)row1 * EMB + h * HD + col + 1] = o[nt][3] * inv1;
    }
}

/* ------------------------------------------------------------------ */
extern "C" void kernel_launch(void* const* d_in, const int* in_sizes, int n_in,
                              void* d_out, int out_size)
{
    const float* x       = (const float*)d_in[0];
    const float* k_cache = (const float*)d_in[1];
    const float* v_cache = (const float*)d_in[2];
    const float* mask    = (const float*)d_in[3];
    const float* wq = (const float*)d_in[4];
    const float* bq = (const float*)d_in[5];
    const float* wk = (const float*)d_in[6];
    const float* bk = (const float*)d_in[7];
    const float* wv = (const float*)d_in[8];
    const float* bv = (const float*)d_in[9];
    const float* wo = (const float*)d_in[10];
    const float* bo = (const float*)d_in[11];

    float* out = (float*)d_out;
    long long need = (long long)MROWS * EMB + 2LL * BSZ * KVLEN * EMB;
    int write_cache = ((long long)out_size >= need) ? 1 : 0;
    float* okc = out + (size_t)MROWS * EMB;
    float* ovc = okc + (size_t)BSZ * KVLEN * EMB;

    cudaFuncSetAttribute(attn_kernel,
                         cudaFuncAttributeMaxDynamicSharedMemorySize, ATT_SMEM);
    cudaFuncSetAttribute(qkv_kernel,
                         cudaFuncAttributeMaxDynamicSharedMemorySize, GEMM_SMEM);
    cudaFuncSetAttribute(proj_kernel,
                         cudaFuncAttributeMaxDynamicSharedMemorySize, GEMM_SMEM);

    if (write_cache) {
        size_t bytes = (size_t)KVOLD * EMB * sizeof(float);
        for (int bb = 0; bb < BSZ; bb++) {
            cudaMemcpyAsync(okc + (size_t)bb * KVLEN * EMB,
                            k_cache + (size_t)bb * KVLEN * EMB,
                            bytes, cudaMemcpyDeviceToDevice, 0);
            cudaMemcpyAsync(ovc + (size_t)bb * KVLEN * EMB,
                            v_cache + (size_t)bb * KVLEN * EMB,
                            bytes, cudaMemcpyDeviceToDevice, 0);
        }
    }

    convert5_kernel<<<dim3(4096, 5), 256>>>(x, wq, wk, wv, wo);
    qkv_kernel<<<dim3(48, 16), 256, GEMM_SMEM>>>(bq, bk, bv, okc, ovc, write_cache);
    attn_kernel<<<dim3(4, 16, 4), 512, ATT_SMEM>>>(k_cache, v_cache, mask);
    convert_attn_kernel<<<4096, 256>>>();
    proj_kernel<<<dim3(16, 16), 256, GEMM_SMEM>>>(bo, out);
}

// round 6
// speedup vs baseline: 3.3271x; 1.0187x over previous
#include <cuda_runtime.h>

#define BSZ   4
#define TGT   512
#define KVLEN 4096
#define KVOLD (KVLEN - TGT)   /* 3584 */
#define EMB   2048
#define NH    16
#define HD    128
#define MROWS (BSZ * TGT)     /* 2048 */
#define SLOT  (EMB * EMB)     /* 4M u32 per matrix */
#define QSCALE 0.08838834764831845f  /* 128^-0.5 */

/* scratch (static device arrays: allocation-free per harness rules) */
__device__ float g_q[MROWS * EMB];
__device__ float g_k[MROWS * EMB];
__device__ float g_v[MROWS * EMB];
/* permuted tf32 operands: 0=x(A) 1=wq(B) 2=wk(B) 3=wv(B) 4=wo(B) 5=attn(A) */
__device__ unsigned g_p[6 * SLOT];

/* ---------------- helpers ---------------- */
__device__ __forceinline__ unsigned f2tf(float f) {
    unsigned u;
    asm("cvt.rna.tf32.f32 %0, %1;" : "=r"(u) : "f"(f));
    return u;
}
__device__ __forceinline__ void mma4(float c[4], const uint4& a, unsigned b0, unsigned b1) {
    asm("mma.sync.aligned.m16n8k8.row.col.f32.tf32.tf32.f32 "
        "{%0,%1,%2,%3},{%4,%5,%6,%7},{%8,%9},{%0,%1,%2,%3};"
        : "+f"(c[0]), "+f"(c[1]), "+f"(c[2]), "+f"(c[3])
        : "r"(a.x), "r"(a.y), "r"(a.z), "r"(a.w), "r"(b0), "r"(b1));
}
__device__ __forceinline__ unsigned sm_u32(const void* p) {
    return (unsigned)__cvta_generic_to_shared(p);
}
__device__ __forceinline__ void cp16(unsigned dst, const void* src) {
    asm volatile("cp.async.cg.shared.global [%0], [%1], 16;" :: "r"(dst), "l"(src));
}
#define CP_COMMIT() asm volatile("cp.async.commit_group;")
#define CP_WAIT(n)  asm volatile("cp.async.wait_group %0;" :: "n"(n))
#define BAR_PAIR(id) asm volatile("bar.sync %0, 64;" :: "r"(id) : "memory")

/* ---------------- permute/convert kernels ----------------
   Fragment layout per matrix (2048x2048 row-major src):
   dst_uint4[(MI*256 + KSL)*32 + lane], MI = row/16, KSL = col/8,
   lane = g*4+tg (g=0..7, tg=0..3).
   A-type: {src[r][c], src[r+8][c], src[r][c+4], src[r+8][c+4]}
   B-type: {src[r][c], src[r][c+4], src[r+8][c], src[r+8][c+4]}
   with r = 16*MI+g, c = 8*KSL+tg. All values tf32-rounded.       */
__device__ __forceinline__ void permute_one(const float* __restrict__ src,
                                            uint4* __restrict__ dst,
                                            unsigned gid, int btype)
{
    unsigned lane = gid & 31, KSL = (gid >> 5) & 255, MI = gid >> 13;
    unsigned g = lane >> 2, tg = lane & 3;
    const float* p = src + (size_t)(MI * 16 + g) * EMB + KSL * 8 + tg;
    float v0 = p[0], v1 = p[8 * EMB], v2 = p[4], v3 = p[8 * EMB + 4];
    uint4 u;
    if (btype) { u.x = f2tf(v0); u.y = f2tf(v2); u.z = f2tf(v1); u.w = f2tf(v3); }
    else       { u.x = f2tf(v0); u.y = f2tf(v1); u.z = f2tf(v2); u.w = f2tf(v3); }
    dst[gid] = u;
}

__global__ void __launch_bounds__(256) convert5_kernel(
    const float* __restrict__ x,  const float* __restrict__ wq,
    const float* __restrict__ wk, const float* __restrict__ wv,
    const float* __restrict__ wo)
{
    int slot = blockIdx.y;
    const float* src = (slot == 0) ? x : (slot == 1) ? wq :
                       (slot == 2) ? wk : (slot == 3) ? wv : wo;
    unsigned gid = blockIdx.x * 256 + threadIdx.x;
    permute_one(src, (uint4*)(g_p + (size_t)slot * SLOT), gid, slot != 0);
}

/* ---------------- dense GEMM: C[128,128] = A @ B^T, pre-permuted tf32 ----
   block 256 thr (8 warps, wm2 x wn4), k-tile 32 (4 slices), 3-stage cp.async. */
#define GSTG 2048   /* uint4 per stage */
#define GEMM_SMEM (3 * GSTG * 16)

__device__ __forceinline__ void gemm_main(
    const uint4* __restrict__ Ag, const uint4* __restrict__ Bg,
    float c[4][4][4], uint4* S, int tid)
{
    const int lane = tid & 31, wid = tid >> 5;
    const int wm = wid >> 2, wn = wid & 3;

    for (int st = 0; st < 2; st++) {
        for (int i = 0; i < 8; i++) {
            int ch = tid + i * 256;
            int half = ch >> 10, cc = ch & 1023;
            int mi = cc >> 7, rest = cc & 127;
            const uint4* src = (half ? Bg : Ag) + (size_t)mi * 8192 + st * 128 + rest;
            cp16(sm_u32(S + st * GSTG + half * 1024 + cc), src);
        }
        CP_COMMIT();
    }

    for (int kt = 0; kt < 64; kt++) {
        if (kt < 63) CP_WAIT(1); else CP_WAIT(0);
        __syncthreads();

        if (kt + 2 < 64) {
            int st = (kt + 2) % 3;
            for (int i = 0; i < 8; i++) {
                int ch = tid + i * 256;
                int half = ch >> 10, cc = ch & 1023;
                int mi = cc >> 7, rest = cc & 127;
                const uint4* src = (half ? Bg : Ag) + (size_t)mi * 8192 + (kt + 2) * 128 + rest;
                cp16(sm_u32(S + st * GSTG + half * 1024 + cc), src);
            }
            CP_COMMIT();
        }

        const uint4* Af = S + (kt % 3) * GSTG;
        const uint4* Bf = Af + 1024;
        #pragma unroll
        for (int ks = 0; ks < 4; ks++) {
            uint4 a[4], bu[2];
            #pragma unroll
            for (int mt = 0; mt < 4; mt++)
                a[mt] = Af[((wm * 4 + mt) * 4 + ks) * 32 + lane];
            #pragma unroll
            for (int p = 0; p < 2; p++)
                bu[p] = Bf[((wn * 2 + p) * 4 + ks) * 32 + lane];
            #pragma unroll
            for (int mt = 0; mt < 4; mt++) {
                mma4(c[mt][0], a[mt], bu[0].x, bu[0].y);
                mma4(c[mt][1], a[mt], bu[0].z, bu[0].w);
                mma4(c[mt][2], a[mt], bu[1].x, bu[1].y);
                mma4(c[mt][3], a[mt], bu[1].z, bu[1].w);
            }
        }
    }
}

/* Fused QKV: grid (48,16): sel = nb>>4, nblk = nb&15 */
__global__ void __launch_bounds__(256, 2) qkv_kernel(
    const float* __restrict__ bq, const float* __restrict__ bk,
    const float* __restrict__ bv,
    float* __restrict__ okc, float* __restrict__ ovc, int write_cache)
{
    extern __shared__ uint4 S[];
    const int tid = threadIdx.x;
    const int lane = tid & 31, wid = tid >> 5;
    const int g = lane >> 2, tg = lane & 3;
    const int wm = wid >> 2, wn = wid & 3;
    const int nb = blockIdx.x, mb = blockIdx.y;
    const int sel = nb >> 4, nblk = nb & 15;
    const float* bias = (sel == 0) ? bq : (sel == 1) ? bk : bv;

    const uint4* Ag = (const uint4*)(g_p) + (size_t)(mb * 8) * 8192;
    const uint4* Bg = (const uint4*)(g_p + (size_t)(1 + sel) * SLOT) + (size_t)(nblk * 8) * 8192;

    float c[4][4][4] = {};
    gemm_main(Ag, Bg, c, S, tid);

    #pragma unroll
    for (int mt = 0; mt < 4; mt++) {
        #pragma unroll
        for (int nt = 0; nt < 4; nt++) {
            int col = nblk * 128 + wn * 32 + nt * 8 + 2 * tg;
            #pragma unroll
            for (int half = 0; half < 2; half++) {
                int m = mb * 128 + wm * 64 + mt * 16 + g + half * 8;
                float v0 = c[mt][nt][half * 2 + 0] + bias[col];
                float v1 = c[mt][nt][half * 2 + 1] + bias[col + 1];
                if (sel == 0) {
                    g_q[(size_t)m * EMB + col]     = v0 * QSCALE;
                    g_q[(size_t)m * EMB + col + 1] = v1 * QSCALE;
                } else {
                    float* dst = (sel == 1) ? g_k : g_v;
                    dst[(size_t)m * EMB + col]     = v0;
                    dst[(size_t)m * EMB + col + 1] = v1;
                    if (write_cache) {
                        int bidx = m >> 9, t = m & 511;
                        float* cd = (sel == 1) ? okc : ovc;
                        size_t o = ((size_t)bidx * KVLEN + KVOLD + t) * EMB + col;
                        cd[o] = v0; cd[o + 1] = v1;
                    }
                }
            }
        }
    }
}

/* Output projection: grid (16,16). A = permuted attn (slot 5). */
__global__ void __launch_bounds__(256, 2) proj_kernel(
    const float* __restrict__ bo, float* __restrict__ out)
{
    extern __shared__ uint4 S[];
    const int tid = threadIdx.x;
    const int lane = tid & 31, wid = tid >> 5;
    const int g = lane >> 2, tg = lane & 3;
    const int wm = wid >> 2, wn = wid & 3;
    const int nblk = blockIdx.x, mb = blockIdx.y;

    const uint4* Ag = (const uint4*)(g_p + 5 * (size_t)SLOT) + (size_t)(mb * 8) * 8192;
    const uint4* Bg = (const uint4*)(g_p + 4 * (size_t)SLOT) + (size_t)(nblk * 8) * 8192;

    float c[4][4][4] = {};
    gemm_main(Ag, Bg, c, S, tid);

    #pragma unroll
    for (int mt = 0; mt < 4; mt++)
        #pragma unroll
        for (int nt = 0; nt < 4; nt++) {
            int col = nblk * 128 + wn * 32 + nt * 8 + 2 * tg;
            #pragma unroll
            for (int half = 0; half < 2; half++) {
                int m = mb * 128 + wm * 64 + mt * 16 + g + half * 8;
                out[(size_t)m * EMB + col]     = c[mt][nt][half * 2 + 0] + bo[col];
                out[(size_t)m * EMB + col + 1] = c[mt][nt][half * 2 + 1] + bo[col + 1];
            }
        }
}

/* ---------------- flash attention, permuted fragments ----------------
   512 thr, 16 warps (wm8 x wn2). Q tile 128 rows, KV tile 64.
   smem (uint4): Qp[4096] | Kp[2x2048] | Vp[2x2048] | Pp[2048]
   = 14336 uint4 = 229376 B dynamic. Kp/Vp double-buffered ->
   only ONE full __syncthreads per KV tile.
   blockIdx.z == BSZ -> cache-copier blocks (ride attention's idle wave-2). */
#define OQ 0
#define OK 4096
#define OV 8192
#define OP 12288
#define ATT_SMEM (14336 * 16)

__global__ void __launch_bounds__(512, 1) attn_kernel(
    const float* __restrict__ kc_in, const float* __restrict__ vc_in,
    const float* __restrict__ mask,
    float* __restrict__ okc, float* __restrict__ ovc, int write_cache)
{
    /* ---- copier plane: absorb the old-cache copy ---- */
    if (blockIdx.z == BSZ) {
        if (write_cache) {
            const int cb = blockIdx.x + gridDim.x * blockIdx.y;   /* 0..63 */
            const int N4 = KVOLD * EMB / 4;                        /* per-batch float4 */
            #pragma unroll 1
            for (int b = 0; b < BSZ; b++) {
                const float4* sk = (const float4*)(kc_in + (size_t)b * KVLEN * EMB);
                const float4* sv = (const float4*)(vc_in + (size_t)b * KVLEN * EMB);
                float4* dk = (float4*)(okc + (size_t)b * KVLEN * EMB);
                float4* dv = (float4*)(ovc + (size_t)b * KVLEN * EMB);
                for (int i = cb * 512 + (int)threadIdx.x; i < N4; i += 64 * 512) {
                    dk[i] = sk[i];
                    dv[i] = sv[i];
                }
            }
        }
        return;
    }

    extern __shared__ uint4 smq[];
    uint4* Qp = smq + OQ;
    uint4* Pp = smq + OP;
    __shared__ float pmax[2][128], psum[2][128];

    const int tid  = threadIdx.x;
    const int lane = tid & 31, wid = tid >> 5;
    const int g = lane >> 2, tg = lane & 3;
    const int wm = wid >> 1, wn = wid & 1;
    const int qt = blockIdx.x, h = blockIdx.y, b = blockIdx.z;

    const int r0 = wm * 16 + g;
    const int r1 = r0 + 8;
    const int cb = wn * 32;

    const float* kold = kc_in + (size_t)b * KVLEN * EMB + h * HD;
    const float* vold = vc_in + (size_t)b * KVLEN * EMB + h * HD;
    const float* knew = g_k + (size_t)b * TGT * EMB + h * HD;
    const float* vnew = g_v + (size_t)b * TGT * EMB + h * HD;
    const float* mbase = mask + (size_t)(qt * 128) * KVLEN;

    /* load + permute Q (A-type): 128 grps, warp w owns grps w*8..w*8+7 */
    {
        const float* qb = g_q + (size_t)(b * TGT + qt * 128) * EMB + h * HD;
        #pragma unroll
        for (int q = 0; q < 8; q++) {
            int G = wid * 8 + q;
            int mi = G >> 4, ksl = G & 15;
            const float* p = qb + (size_t)(mi * 16 + g) * EMB + ksl * 8 + tg;
            uint4 u;
            u.x = f2tf(p[0]); u.y = f2tf(p[8 * EMB]);
            u.z = f2tf(p[4]); u.w = f2tf(p[8 * EMB + 4]);
            Qp[G * 32 + lane] = u;
        }
    }

    /* prefetch K(0)/V(0) into registers */
    float kreg[4][4], vreg[4][4];
    #pragma unroll
    for (int q = 0; q < 4; q++) {
        int G = wid * 4 + q;
        { int pi = G >> 4, ksl = G & 15;
          const float* p = kold + (size_t)(pi * 16 + g) * EMB + ksl * 8 + tg;
          kreg[q][0] = p[0]; kreg[q][1] = p[4];
          kreg[q][2] = p[8 * EMB]; kreg[q][3] = p[8 * EMB + 4]; }
        { int pi = G >> 3, ksl = G & 7;
          const float* p = vold + (size_t)(ksl * 8 + tg) * EMB + pi * 16 + g;
          vreg[q][0] = p[0]; vreg[q][1] = p[4 * EMB];
          vreg[q][2] = p[8]; vreg[q][3] = p[4 * EMB + 8]; }
    }

    float m0 = -1e30f, m1 = -1e30f, l0 = 0.f, l1 = 0.f;
    float o[8][4] = {};

    for (int t = 0; t < KVLEN / 64; t++) {
        const int kt0 = t * 64;
        uint4* Kc = smq + OK + (t & 1) * 2048;
        uint4* Vc = smq + OV + (t & 1) * 2048;

        /* STS K(t), V(t) permuted into buffer t&1 */
        #pragma unroll
        for (int q = 0; q < 4; q++) {
            int G = wid * 4 + q;
            uint4 uk, uv;
            uk.x = f2tf(kreg[q][0]); uk.y = f2tf(kreg[q][1]);
            uk.z = f2tf(kreg[q][2]); uk.w = f2tf(kreg[q][3]);
            uv.x = f2tf(vreg[q][0]); uv.y = f2tf(vreg[q][1]);
            uv.z = f2tf(vreg[q][2]); uv.w = f2tf(vreg[q][3]);
            Kc[G * 32 + lane] = uk;
            Vc[G * 32 + lane] = uv;
        }

        /* mask prefetch */
        float2 mA[4], mB[4];
        #pragma unroll
        for (int nt = 0; nt < 4; nt++) {
            int col = cb + nt * 8 + 2 * tg;
            mA[nt] = *(const float2*)(mbase + (size_t)r0 * KVLEN + kt0 + col);
            mB[nt] = *(const float2*)(mbase + (size_t)r1 * KVLEN + kt0 + col);
        }
        __syncthreads();   /* the only full barrier per tile */

        /* S = Q K^T */
        float s[4][4] = {};
        #pragma unroll
        for (int ks = 0; ks < 16; ks++) {
            uint4 a  = Qp[(wm * 16 + ks) * 32 + lane];
            uint4 b0 = Kc[((2 * wn) * 16 + ks) * 32 + lane];
            uint4 b1 = Kc[((2 * wn + 1) * 16 + ks) * 32 + lane];
            mma4(s[0], a, b0.x, b0.y);
            mma4(s[1], a, b0.z, b0.w);
            mma4(s[2], a, b1.x, b1.y);
            mma4(s[3], a, b1.z, b1.w);
        }

        #pragma unroll
        for (int nt = 0; nt < 4; nt++) {
            s[nt][0] += mA[nt].x; s[nt][1] += mA[nt].y;
            s[nt][2] += mB[nt].x; s[nt][3] += mB[nt].y;
        }

        /* row max (quad reduce) */
        float mx0 = -1e30f, mx1 = -1e30f;
        #pragma unroll
        for (int nt = 0; nt < 4; nt++) {
            mx0 = fmaxf(mx0, fmaxf(s[nt][0], s[nt][1]));
            mx1 = fmaxf(mx1, fmaxf(s[nt][2], s[nt][3]));
        }
        mx0 = fmaxf(mx0, __shfl_xor_sync(0xffffffffu, mx0, 1));
        mx0 = fmaxf(mx0, __shfl_xor_sync(0xffffffffu, mx0, 2));
        mx1 = fmaxf(mx1, __shfl_xor_sync(0xffffffffu, mx1, 1));
        mx1 = fmaxf(mx1, __shfl_xor_sync(0xffffffffu, mx1, 2));
        if (tg == 0) { pmax[wn][r0] = mx0; pmax[wn][r1] = mx1; }
        BAR_PAIR(1 + wm);

        float mn0 = fmaxf(m0, fmaxf(pmax[0][r0], pmax[1][r0]));
        float mn1 = fmaxf(m1, fmaxf(pmax[0][r1], pmax[1][r1]));
        float s0s = 0.f, s1s = 0.f;
        unsigned* Pu = (unsigned*)Pp;
        const int pbase = (wm * 8 + wn * 4) * 128;
        const int eoff = (g * 4 + (tg & 1) * 2) * 4 + (tg >> 1) * 2;
        #pragma unroll
        for (int nt = 0; nt < 4; nt++) {
            s[nt][0] = __expf(s[nt][0] - mn0);
            s[nt][1] = __expf(s[nt][1] - mn0);
            s[nt][2] = __expf(s[nt][2] - mn1);
            s[nt][3] = __expf(s[nt][3] - mn1);
            s0s += s[nt][0] + s[nt][1];
            s1s += s[nt][2] + s[nt][3];
            int bb = pbase + nt * 128 + eoff;
            Pu[bb + 0] = f2tf(s[nt][0]);
            Pu[bb + 4] = f2tf(s[nt][1]);
            Pu[bb + 1] = f2tf(s[nt][2]);
            Pu[bb + 5] = f2tf(s[nt][3]);
        }
        s0s += __shfl_xor_sync(0xffffffffu, s0s, 1);
        s0s += __shfl_xor_sync(0xffffffffu, s0s, 2);
        s1s += __shfl_xor_sync(0xffffffffu, s1s, 1);
        s1s += __shfl_xor_sync(0xffffffffu, s1s, 2);
        if (tg == 0) { psum[wn][r0] = s0s; psum[wn][r1] = s1s; }
        BAR_PAIR(1 + wm);

        float sc0 = __expf(m0 - mn0), sc1 = __expf(m1 - mn1);
        l0 = l0 * sc0 + psum[0][r0] + psum[1][r0];
        l1 = l1 * sc1 + psum[0][r1] + psum[1][r1];
        m0 = mn0; m1 = mn1;
        #pragma unroll
        for (int nt = 0; nt < 8; nt++) {
            o[nt][0] *= sc0; o[nt][1] *= sc0;
            o[nt][2] *= sc1; o[nt][3] *= sc1;
        }

        /* prefetch K/V(t+1) */
        if (t < KVLEN / 64 - 1) {
            int nk = kt0 + 64;
            const float* ks_ = (nk < KVOLD) ? kold + (size_t)nk * EMB
                                            : knew + (size_t)(nk - KVOLD) * EMB;
            const float* vs_ = (nk < KVOLD) ? vold + (size_t)nk * EMB
                                            : vnew + (size_t)(nk - KVOLD) * EMB;
            #pragma unroll
            for (int q = 0; q < 4; q++) {
                int G = wid * 4 + q;
                { int pi = G >> 4, ksl = G & 15;
                  const float* p = ks_ + (size_t)(pi * 16 + g) * EMB + ksl * 8 + tg;
                  kreg[q][0] = p[0]; kreg[q][1] = p[4];
                  kreg[q][2] = p[8 * EMB]; kreg[q][3] = p[8 * EMB + 4]; }
                { int pi = G >> 3, ksl = G & 7;
                  const float* p = vs_ + (size_t)(ksl * 8 + tg) * EMB + pi * 16 + g;
                  vreg[q][0] = p[0]; vreg[q][1] = p[4 * EMB];
                  vreg[q][2] = p[8]; vreg[q][3] = p[4 * EMB + 8]; }
            }
        }

        /* O += P V */
        #pragma unroll
        for (int ks = 0; ks < 8; ks++) {
            uint4 a  = Pp[(wm * 8 + ks) * 32 + lane];
            uint4 v0 = Vc[((4 * wn + 0) * 8 + ks) * 32 + lane];
            uint4 v1 = Vc[((4 * wn + 1) * 8 + ks) * 32 + lane];
            uint4 v2 = Vc[((4 * wn + 2) * 8 + ks) * 32 + lane];
            uint4 v3 = Vc[((4 * wn + 3) * 8 + ks) * 32 + lane];
            mma4(o[0], a, v0.x, v0.y);
            mma4(o[1], a, v0.z, v0.w);
            mma4(o[2], a, v1.x, v1.y);
            mma4(o[3], a, v1.z, v1.w);
            mma4(o[4], a, v2.x, v2.y);
            mma4(o[5], a, v2.z, v2.w);
            mma4(o[6], a, v3.x, v3.y);
            mma4(o[7], a, v3.z, v3.w);
        }
        /* no end-of-tile barrier: next tile writes the other K/V buffer,
           and Pp/pmax/psum reuse is ordered by the top __syncthreads. */
    }

    /* ---- fused epilogue: normalize + write permuted A-layout to g_p slot 5 ---- */
    __syncthreads();                       /* all PV reads done before staging reuse */
    float* St = (float*)(smq + OK);        /* 128 x 132 floats = 67.6KB (K/V region) */
    {
        float inv0 = 1.f / l0, inv1 = 1.f / l1;
        #pragma unroll
        for (int nt = 0; nt < 8; nt++) {
            int col = wn * 64 + nt * 8 + 2 * tg;
            St[r0 * 132 + col]     = o[nt][0] * inv0;
            St[r0 * 132 + col + 1] = o[nt][1] * inv0;
            St[r1 * 132 + col]     = o[nt][2] * inv1;
            St[r1 * 132 + col + 1] = o[nt][3] * inv1;
        }
    }
    __syncthreads();
    {
        uint4* gp5 = (uint4*)(g_p + 5 * (size_t)SLOT);
        const int KSL = wid;               /* 16 warps -> 16 k-slices of this h */
        const int gMIb = b * 32 + qt * 8;  /* (b*TGT + qt*128)/16 */
        #pragma unroll
        for (int MI = 0; MI < 8; MI++) {
            int r = MI * 16 + g, c = KSL * 8 + tg;
            uint4 u;
            u.x = f2tf(St[r * 132 + c]);
            u.y = f2tf(St[(r + 8) * 132 + c]);
            u.z = f2tf(St[r * 132 + c + 4]);
            u.w = f2tf(St[(r + 8) * 132 + c + 4]);
            gp5[((size_t)(gMIb + MI) * 256 + (h * 16 + KSL)) * 32 + lane] = u;
        }
    }
}

/* ------------------------------------------------------------------ */
extern "C" void kernel_launch(void* const* d_in, const int* in_sizes, int n_in,
                              void* d_out, int out_size)
{
    const float* x       = (const float*)d_in[0];
    const float* k_cache = (const float*)d_in[1];
    const float* v_cache = (const float*)d_in[2];
    const float* mask    = (const float*)d_in[3];
    const float* wq = (const float*)d_in[4];
    const float* bq = (const float*)d_in[5];
    const float* wk = (const float*)d_in[6];
    const float* bk = (const float*)d_in[7];
    const float* wv = (const float*)d_in[8];
    const float* bv = (const float*)d_in[9];
    const float* wo = (const float*)d_in[10];
    const float* bo = (const float*)d_in[11];

    float* out = (float*)d_out;
    long long need = (long long)MROWS * EMB + 2LL * BSZ * KVLEN * EMB;
    int write_cache = ((long long)out_size >= need) ? 1 : 0;
    float* okc = out + (size_t)MROWS * EMB;
    float* ovc = okc + (size_t)BSZ * KVLEN * EMB;

    cudaFuncSetAttribute(attn_kernel,
                         cudaFuncAttributeMaxDynamicSharedMemorySize, ATT_SMEM);
    cudaFuncSetAttribute(qkv_kernel,
                         cudaFuncAttributeMaxDynamicSharedMemorySize, GEMM_SMEM);
    cudaFuncSetAttribute(proj_kernel,
                         cudaFuncAttributeMaxDynamicSharedMemorySize, GEMM_SMEM);

    convert5_kernel<<<dim3(4096, 5), 256>>>(x, wq, wk, wv, wo);
    qkv_kernel<<<dim3(48, 16), 256, GEMM_SMEM>>>(bq, bk, bv, okc, ovc, write_cache);
    attn_kernel<<<dim3(4, 16, BSZ + 1), 512, ATT_SMEM>>>(k_cache, v_cache, mask,
                                                         okc, ovc, write_cache);
    proj_kernel<<<dim3(16, 16), 256, GEMM_SMEM>>>(bo, out);
}

// round 9
// speedup vs baseline: 4.1971x; 1.2615x over previous
#include <cuda_runtime.h>

#define BSZ   4
#define TGT   512
#define KVLEN 4096
#define KVOLD (KVLEN - TGT)   /* 3584 */
#define EMB   2048
#define NH    16
#define HD    128
#define MROWS (BSZ * TGT)     /* 2048 */
#define SLOT  (EMB * EMB)     /* 4M u32 per matrix */
#define QSCALE 0.08838834764831845f  /* 128^-0.5 */

/* scratch (static device arrays: allocation-free per harness rules) */
__device__ float g_q[MROWS * EMB];
__device__ float g_k[MROWS * EMB];
__device__ float g_v[MROWS * EMB];
/* permuted tf32 operands: 0=x(A) 1=wq(B) 2=wk(B) 3=wv(B) 4=wo(B) 5=attn(A) */
__device__ unsigned g_p[6 * SLOT];
/* permuted tf32 KV cache, fragment layout, per (b,h): 131072 uint4 */
__device__ uint4 g_kp[64 * 131072];
__device__ uint4 g_vp[64 * 131072];

/* ---------------- helpers ---------------- */
__device__ __forceinline__ unsigned f2tf(float f) {
    unsigned u;
    asm("cvt.rna.tf32.f32 %0, %1;" : "=r"(u) : "f"(f));
    return u;
}
__device__ __forceinline__ void mma4(float c[4], const uint4& a, unsigned b0, unsigned b1) {
    asm("mma.sync.aligned.m16n8k8.row.col.f32.tf32.tf32.f32 "
        "{%0,%1,%2,%3},{%4,%5,%6,%7},{%8,%9},{%0,%1,%2,%3};"
        : "+f"(c[0]), "+f"(c[1]), "+f"(c[2]), "+f"(c[3])
        : "r"(a.x), "r"(a.y), "r"(a.z), "r"(a.w), "r"(b0), "r"(b1));
}
__device__ __forceinline__ unsigned sm_u32(const void* p) {
    return (unsigned)__cvta_generic_to_shared(p);
}
__device__ __forceinline__ void cp16(unsigned dst, const void* src) {
    asm volatile("cp.async.cg.shared.global [%0], [%1], 16;" :: "r"(dst), "l"(src));
}
#define CP_COMMIT() asm volatile("cp.async.commit_group;")
#define CP_WAIT(n)  asm volatile("cp.async.wait_group %0;" :: "n"(n))
#define BAR_PAIR(id) asm volatile("bar.sync %0, 64;" :: "r"(id) : "memory")

/* ---------------- dense-operand permute (A/B fragment layouts) ---------------- */
__device__ __forceinline__ void permute_one(const float* __restrict__ src,
                                            uint4* __restrict__ dst,
                                            unsigned gid, int btype)
{
    unsigned lane = gid & 31, KSL = (gid >> 5) & 255, MI = gid >> 13;
    unsigned g = lane >> 2, tg = lane & 3;
    const float* p = src + (size_t)(MI * 16 + g) * EMB + KSL * 8 + tg;
    float v0 = p[0], v1 = p[8 * EMB], v2 = p[4], v3 = p[8 * EMB + 4];
    uint4 u;
    if (btype) { u.x = f2tf(v0); u.y = f2tf(v2); u.z = f2tf(v1); u.w = f2tf(v3); }
    else       { u.x = f2tf(v0); u.y = f2tf(v1); u.z = f2tf(v2); u.w = f2tf(v3); }
    dst[gid] = u;
}

__global__ void __launch_bounds__(256) convert5_kernel(
    const float* __restrict__ x,  const float* __restrict__ wq,
    const float* __restrict__ wk, const float* __restrict__ wv,
    const float* __restrict__ wo)
{
    int slot = blockIdx.y;
    const float* src = (slot == 0) ? x : (slot == 1) ? wq :
                       (slot == 2) ? wk : (slot == 3) ? wv : wo;
    unsigned gid = blockIdx.x * 256 + threadIdx.x;
    permute_one(src, (uint4*)(g_p + (size_t)slot * SLOT), gid, slot != 0);
}

/* ---------------- KV tile permute helper (64 j-rows x 128 d, staged in smem) ----
   Ts: 64x132 f32 staging. Writes K frags (B-type over [j][d]) or V frags
   (B-type over [d][j]) for global tile index tt.                                */
__device__ __forceinline__ void kv_permute_tile(
    const float* __restrict__ src,   /* + row0*EMB + h*HD pre-applied */
    float* Ts, int tt, int bh, int isV, int tid)
{
    const int lane = tid & 31, g = lane >> 2, tg = lane & 3;
    __syncthreads();
    #pragma unroll
    for (int p = 0; p < 8; p++) {
        int idx = tid + p * 256;
        int r = idx >> 5, c4 = (idx & 31) << 2;
        *(float4*)&Ts[r * 132 + c4] = *(const float4*)(src + (size_t)r * EMB + c4);
    }
    __syncthreads();
    if (!isV) {
        uint4* dst = g_kp + (size_t)bh * 131072;
        #pragma unroll
        for (int p = 0; p < 8; p++) {
            int idx = tid + p * 256;
            int pi_l = idx >> 9, ksl = (idx >> 5) & 15;
            int j0 = pi_l * 16, c = ksl * 8 + tg;
            uint4 u;
            u.x = f2tf(Ts[(j0 + g) * 132 + c]);
            u.y = f2tf(Ts[(j0 + g) * 132 + c + 4]);
            u.z = f2tf(Ts[(j0 + g + 8) * 132 + c]);
            u.w = f2tf(Ts[(j0 + g + 8) * 132 + c + 4]);
            dst[(size_t)(tt * 4 + pi_l) * 512 + ksl * 32 + lane] = u;
        }
    } else {
        uint4* dst = g_vp + (size_t)bh * 131072;
        #pragma unroll
        for (int p = 0; p < 8; p++) {
            int idx = tid + p * 256;
            int pi_d = idx >> 8, kslj = (idx >> 5) & 7;
            int d0 = pi_d * 16, j0 = kslj * 8;
            uint4 u;
            u.x = f2tf(Ts[(j0 + tg) * 132 + d0 + g]);
            u.y = f2tf(Ts[(j0 + tg + 4) * 132 + d0 + g]);
            u.z = f2tf(Ts[(j0 + tg) * 132 + d0 + g + 8]);
            u.w = f2tf(Ts[(j0 + tg + 4) * 132 + d0 + g + 8]);
            dst[(size_t)pi_d * 16384 + (size_t)(tt * 8 + kslj) * 32 + lane] = u;
        }
    }
}

/* permute NEW kv region (from g_k/g_v). 1024 blocks. */
__global__ void __launch_bounds__(256) permute_new_kernel()
{
    __shared__ float Ts[64 * 132];
    int job = blockIdx.x;               /* 0..1023 */
    int isV = job >= 512;
    int jj = job & 511;
    int bh = jj >> 3, tl = jj & 7;
    int b = bh >> 4, h = bh & 15;
    const float* src = (isV ? g_v : g_k) + ((size_t)(b * TGT) + tl * 64) * EMB + h * HD;
    kv_permute_tile(src, Ts, 56 + tl, bh, isV, threadIdx.x);
}

/* ---------------- dense GEMM: C[128,128] = A @ B^T, pre-permuted tf32 ---------------- */
#define GSTG 2048   /* uint4 per stage */
#define GEMM_SMEM (3 * GSTG * 16)

__device__ __forceinline__ void gemm_main(
    const uint4* __restrict__ Ag, const uint4* __restrict__ Bg,
    float c[4][4][4], uint4* S, int tid)
{
    const int lane = tid & 31, wid = tid >> 5;
    const int wm = wid >> 2, wn = wid & 3;

    for (int st = 0; st < 2; st++) {
        for (int i = 0; i < 8; i++) {
            int ch = tid + i * 256;
            int half = ch >> 10, cc = ch & 1023;
            int mi = cc >> 7, rest = cc & 127;
            const uint4* src = (half ? Bg : Ag) + (size_t)mi * 8192 + st * 128 + rest;
            cp16(sm_u32(S + st * GSTG + half * 1024 + cc), src);
        }
        CP_COMMIT();
    }

    for (int kt = 0; kt < 64; kt++) {
        if (kt < 63) CP_WAIT(1); else CP_WAIT(0);
        __syncthreads();

        if (kt + 2 < 64) {
            int st = (kt + 2) % 3;
            for (int i = 0; i < 8; i++) {
                int ch = tid + i * 256;
                int half = ch >> 10, cc = ch & 1023;
                int mi = cc >> 7, rest = cc & 127;
                const uint4* src = (half ? Bg : Ag) + (size_t)mi * 8192 + (kt + 2) * 128 + rest;
                cp16(sm_u32(S + st * GSTG + half * 1024 + cc), src);
            }
            CP_COMMIT();
        }

        const uint4* Af = S + (kt % 3) * GSTG;
        const uint4* Bf = Af + 1024;
        #pragma unroll
        for (int ks = 0; ks < 4; ks++) {
            uint4 a[4], bu[2];
            #pragma unroll
            for (int mt = 0; mt < 4; mt++)
                a[mt] = Af[((wm * 4 + mt) * 4 + ks) * 32 + lane];
            #pragma unroll
            for (int p = 0; p < 2; p++)
                bu[p] = Bf[((wn * 2 + p) * 4 + ks) * 32 + lane];
            #pragma unroll
            for (int mt = 0; mt < 4; mt++) {
                mma4(c[mt][0], a[mt], bu[0].x, bu[0].y);
                mma4(c[mt][1], a[mt], bu[0].z, bu[0].w);
                mma4(c[mt][2], a[mt], bu[1].x, bu[1].y);
                mma4(c[mt][3], a[mt], bu[1].z, bu[1].w);
            }
        }
    }
}

/* Fused QKV + interleaved old-KV permute plane.
   grid (96,16): x<48 -> gemm (sel = x>>4, nblk = x&15); x>=48 -> permute jobs. */
__global__ void __launch_bounds__(256, 2) qkv_kernel(
    const float* __restrict__ kc_in, const float* __restrict__ vc_in,
    const float* __restrict__ bq, const float* __restrict__ bk,
    const float* __restrict__ bv,
    float* __restrict__ okc, float* __restrict__ ovc, int write_cache)
{
    extern __shared__ uint4 S[];
    const int tid = threadIdx.x;

    if (blockIdx.x >= 48) {
        /* old-KV permute: 7168 tile jobs over 768 blocks */
        float* Ts = (float*)S;
        int pbid = (blockIdx.x - 48) + 48 * blockIdx.y;
        for (int job = pbid; job < 7168; job += 768) {
            int isV = job >= 3584;
            int jj = isV ? job - 3584 : job;
            int bh = jj / 56, tt = jj % 56;
            int b = bh >> 4, h = bh & 15;
            const float* src = (isV ? vc_in : kc_in)
                + ((size_t)(b * KVLEN) + tt * 64) * EMB + h * HD;
            kv_permute_tile(src, Ts, tt, bh, isV, tid);
        }
        return;
    }

    const int lane = tid & 31, wid = tid >> 5;
    const int g = lane >> 2, tg = lane & 3;
    const int wm = wid >> 2, wn = wid & 3;
    const int nb = blockIdx.x, mb = blockIdx.y;
    const int sel = nb >> 4, nblk = nb & 15;
    const float* bias = (sel == 0) ? bq : (sel == 1) ? bk : bv;

    const uint4* Ag = (const uint4*)(g_p) + (size_t)(mb * 8) * 8192;
    const uint4* Bg = (const uint4*)(g_p + (size_t)(1 + sel) * SLOT) + (size_t)(nblk * 8) * 8192;

    float c[4][4][4] = {};
    gemm_main(Ag, Bg, c, S, tid);

    #pragma unroll
    for (int mt = 0; mt < 4; mt++) {
        #pragma unroll
        for (int nt = 0; nt < 4; nt++) {
            int col = nblk * 128 + wn * 32 + nt * 8 + 2 * tg;
            #pragma unroll
            for (int half = 0; half < 2; half++) {
                int m = mb * 128 + wm * 64 + mt * 16 + g + half * 8;
                float v0 = c[mt][nt][half * 2 + 0] + bias[col];
                float v1 = c[mt][nt][half * 2 + 1] + bias[col + 1];
                if (sel == 0) {
                    g_q[(size_t)m * EMB + col]     = v0 * QSCALE;
                    g_q[(size_t)m * EMB + col + 1] = v1 * QSCALE;
                } else {
                    float* dst = (sel == 1) ? g_k : g_v;
                    dst[(size_t)m * EMB + col]     = v0;
                    dst[(size_t)m * EMB + col + 1] = v1;
                    if (write_cache) {
                        int bidx = m >> 9, t = m & 511;
                        float* cd = (sel == 1) ? okc : ovc;
                        size_t o = ((size_t)bidx * KVLEN + KVOLD + t) * EMB + col;
                        cd[o] = v0; cd[o + 1] = v1;
                    }
                }
            }
        }
    }
}

/* Output projection: grid (16,16). A = permuted attn (slot 5). */
__global__ void __launch_bounds__(256, 2) proj_kernel(
    const float* __restrict__ bo, float* __restrict__ out)
{
    extern __shared__ uint4 S[];
    const int tid = threadIdx.x;
    const int lane = tid & 31, wid = tid >> 5;
    const int g = lane >> 2, tg = lane & 3;
    const int wm = wid >> 2, wn = wid & 3;
    const int nblk = blockIdx.x, mb = blockIdx.y;

    const uint4* Ag = (const uint4*)(g_p + 5 * (size_t)SLOT) + (size_t)(mb * 8) * 8192;
    const uint4* Bg = (const uint4*)(g_p + 4 * (size_t)SLOT) + (size_t)(nblk * 8) * 8192;

    float c[4][4][4] = {};
    gemm_main(Ag, Bg, c, S, tid);

    #pragma unroll
    for (int mt = 0; mt < 4; mt++)
        #pragma unroll
        for (int nt = 0; nt < 4; nt++) {
            int col = nblk * 128 + wn * 32 + nt * 8 + 2 * tg;
            #pragma unroll
            for (int half = 0; half < 2; half++) {
                int m = mb * 128 + wm * 64 + mt * 16 + g + half * 8;
                out[(size_t)m * EMB + col]     = c[mt][nt][half * 2 + 0] + bo[col];
                out[(size_t)m * EMB + col + 1] = c[mt][nt][half * 2 + 1] + bo[col + 1];
            }
        }
}

/* ---------------- flash attention: 256 thr, 8 warps (4 wm x 2 wn)  ----------------
   Warp tiles: S m32n32, PV m32n64. K/V cp.async from pre-permuted global frags.
   smem (uint4): Qp[4096] | K 2x2048 | V 2x2048 | Pp[2048] = 14336 (229376 B).
   blockIdx.z == BSZ -> cache-copier blocks. */
#define OQ 0
#define OK 4096
#define OV 8192
#define OP 12288
#define ATT_SMEM (14336 * 16)
#define NT (KVLEN / 64)

__global__ void __launch_bounds__(256, 1) attn_kernel(
    const float* __restrict__ kc_in, const float* __restrict__ vc_in,
    const float* __restrict__ mask,
    float* __restrict__ okc, float* __restrict__ ovc, int write_cache)
{
    if (blockIdx.z == BSZ) {
        if (write_cache) {
            const int cb = blockIdx.x + gridDim.x * blockIdx.y;   /* 0..63 */
            const int N4 = KVOLD * EMB / 4;
            #pragma unroll 1
            for (int b = 0; b < BSZ; b++) {
                const float4* sk = (const float4*)(kc_in + (size_t)b * KVLEN * EMB);
                const float4* sv = (const float4*)(vc_in + (size_t)b * KVLEN * EMB);
                float4* dk = (float4*)(okc + (size_t)b * KVLEN * EMB);
                float4* dv = (float4*)(ovc + (size_t)b * KVLEN * EMB);
                for (int i = cb * 256 + (int)threadIdx.x; i < N4; i += 64 * 256) {
                    dk[i] = sk[i];
                    dv[i] = sv[i];
                }
            }
        }
        return;
    }

    extern __shared__ uint4 smq[];
    uint4* Qp = smq + OQ;
    uint4* Pp = smq + OP;
    __shared__ float pmax[2][128], psum[2][128];

    const int tid  = threadIdx.x;
    const int lane = tid & 31, wid = tid >> 5;
    const int g = lane >> 2, tg = lane & 3;
    const int wm = wid >> 1, wn = wid & 1;
    const int qt = blockIdx.x, h = blockIdx.y, b = blockIdx.z;

    const uint4* gK = g_kp + (size_t)(b * 16 + h) * 131072;
    const uint4* gV = g_vp + (size_t)(b * 16 + h) * 131072;
    const float* mbase = mask + (size_t)(qt * 128) * KVLEN;

    /* prologue: cp.async K/V tiles 0,1 */
    #pragma unroll
    for (int st = 0; st < 2; st++) {
        #pragma unroll
        for (int p = 0; p < 8; p++) {
            int idx = tid + p * 256;
            cp16(sm_u32(smq + OK + st * 2048 + idx), gK + st * 2048 + idx);
            cp16(sm_u32(smq + OV + st * 2048 + idx),
                 gV + (size_t)(idx >> 8) * 16384 + st * 256 + (idx & 255));
        }
        CP_COMMIT();
    }

    /* Q load + permute: warp w owns frag groups w*16..w*16+15 */
    {
        const float* qb = g_q + (size_t)(b * TGT + qt * 128) * EMB + h * HD;
        #pragma unroll
        for (int q = 0; q < 16; q++) {
            int G = wid * 16 + q;
            int mi = G >> 4, ksl = G & 15;
            const float* p = qb + (size_t)(mi * 16 + g) * EMB + ksl * 8 + tg;
            uint4 u;
            u.x = f2tf(p[0]); u.y = f2tf(p[8 * EMB]);
            u.z = f2tf(p[4]); u.w = f2tf(p[8 * EMB + 4]);
            Qp[G * 32 + lane] = u;
        }
    }

    float m_[2][2], l_[2][2];
    #pragma unroll
    for (int i = 0; i < 2; i++)
        #pragma unroll
        for (int hh = 0; hh < 2; hh++) { m_[i][hh] = -1e30f; l_[i][hh] = 0.f; }
    float o[2][8][4] = {};

    for (int t = 0; t < NT; t++) {
        const uint4* Kc = smq + OK + (t & 1) * 2048;
        const uint4* Vc = smq + OV + (t & 1) * 2048;

        /* mask prefetch: rows wm*32+i*16+hh*8+g, cols wn*32+j*8+2tg */
        float2 mk[2][2][4];
        #pragma unroll
        for (int i = 0; i < 2; i++)
            #pragma unroll
            for (int hh = 0; hh < 2; hh++) {
                int r = wm * 32 + i * 16 + hh * 8 + g;
                #pragma unroll
                for (int j = 0; j < 4; j++)
                    mk[i][hh][j] = *(const float2*)(mbase + (size_t)r * KVLEN
                                                    + t * 64 + wn * 32 + j * 8 + 2 * tg);
            }

        if (t == NT - 1) CP_WAIT(0); else CP_WAIT(1);
        __syncthreads();

        /* S = Q K^T : warp m32 x n32 */
        float s[2][4][4] = {};
        #pragma unroll
        for (int ks = 0; ks < 16; ks++) {
            uint4 a0 = Qp[((2 * wm) * 16 + ks) * 32 + lane];
            uint4 a1 = Qp[((2 * wm + 1) * 16 + ks) * 32 + lane];
            uint4 b0 = Kc[((2 * wn) * 16 + ks) * 32 + lane];
            uint4 b1 = Kc[((2 * wn + 1) * 16 + ks) * 32 + lane];
            mma4(s[0][0], a0, b0.x, b0.y); mma4(s[0][1], a0, b0.z, b0.w);
            mma4(s[0][2], a0, b1.x, b1.y); mma4(s[0][3], a0, b1.z, b1.w);
            mma4(s[1][0], a1, b0.x, b0.y); mma4(s[1][1], a1, b0.z, b0.w);
            mma4(s[1][2], a1, b1.x, b1.y); mma4(s[1][3], a1, b1.z, b1.w);
        }

        /* + mask, row max */
        float mx[2][2];
        #pragma unroll
        for (int i = 0; i < 2; i++) {
            mx[i][0] = -1e30f; mx[i][1] = -1e30f;
            #pragma unroll
            for (int j = 0; j < 4; j++) {
                s[i][j][0] += mk[i][0][j].x; s[i][j][1] += mk[i][0][j].y;
                s[i][j][2] += mk[i][1][j].x; s[i][j][3] += mk[i][1][j].y;
                mx[i][0] = fmaxf(mx[i][0], fmaxf(s[i][j][0], s[i][j][1]));
                mx[i][1] = fmaxf(mx[i][1], fmaxf(s[i][j][2], s[i][j][3]));
            }
            mx[i][0] = fmaxf(mx[i][0], __shfl_xor_sync(0xffffffffu, mx[i][0], 1));
            mx[i][0] = fmaxf(mx[i][0], __shfl_xor_sync(0xffffffffu, mx[i][0], 2));
            mx[i][1] = fmaxf(mx[i][1], __shfl_xor_sync(0xffffffffu, mx[i][1], 1));
            mx[i][1] = fmaxf(mx[i][1], __shfl_xor_sync(0xffffffffu, mx[i][1], 2));
        }
        if (tg == 0) {
            #pragma unroll
            for (int i = 0; i < 2; i++) {
                pmax[wn][wm * 32 + i * 16 + g]     = mx[i][0];
                pmax[wn][wm * 32 + i * 16 + 8 + g] = mx[i][1];
            }
        }
        BAR_PAIR(1 + wm);

        float mn[2][2], ss[2][2];
        unsigned* Pu = (unsigned*)Pp;
        const int eoff = (g * 4 + (tg & 1) * 2) * 4 + (tg >> 1) * 2;
        #pragma unroll
        for (int i = 0; i < 2; i++) {
            #pragma unroll
            for (int hh = 0; hh < 2; hh++) {
                int r = wm * 32 + i * 16 + hh * 8 + g;
                mn[i][hh] = fmaxf(m_[i][hh], fmaxf(pmax[0][r], pmax[1][r]));
                ss[i][hh] = 0.f;
            }
            #pragma unroll
            for (int j = 0; j < 4; j++) {
                s[i][j][0] = __expf(s[i][j][0] - mn[i][0]);
                s[i][j][1] = __expf(s[i][j][1] - mn[i][0]);
                s[i][j][2] = __expf(s[i][j][2] - mn[i][1]);
                s[i][j][3] = __expf(s[i][j][3] - mn[i][1]);
                ss[i][0] += s[i][j][0] + s[i][j][1];
                ss[i][1] += s[i][j][2] + s[i][j][3];
                int bb = ((2 * wm + i) * 8 + 4 * wn + j) * 128 + eoff;
                Pu[bb + 0] = f2tf(s[i][j][0]);
                Pu[bb + 4] = f2tf(s[i][j][1]);
                Pu[bb + 1] = f2tf(s[i][j][2]);
                Pu[bb + 5] = f2tf(s[i][j][3]);
            }
            #pragma unroll
            for (int hh = 0; hh < 2; hh++) {
                ss[i][hh] += __shfl_xor_sync(0xffffffffu, ss[i][hh], 1);
                ss[i][hh] += __shfl_xor_sync(0xffffffffu, ss[i][hh], 2);
            }
        }
        if (tg == 0) {
            #pragma unroll
            for (int i = 0; i < 2; i++) {
                psum[wn][wm * 32 + i * 16 + g]     = ss[i][0];
                psum[wn][wm * 32 + i * 16 + 8 + g] = ss[i][1];
            }
        }
        BAR_PAIR(1 + wm);

        #pragma unroll
        for (int i = 0; i < 2; i++) {
            float sc[2];
            #pragma unroll
            for (int hh = 0; hh < 2; hh++) {
                int r = wm * 32 + i * 16 + hh * 8 + g;
                sc[hh] = __expf(m_[i][hh] - mn[i][hh]);
                l_[i][hh] = l_[i][hh] * sc[hh] + psum[0][r] + psum[1][r];
                m_[i][hh] = mn[i][hh];
            }
            #pragma unroll
            for (int j2 = 0; j2 < 8; j2++) {
                o[i][j2][0] *= sc[0]; o[i][j2][1] *= sc[0];
                o[i][j2][2] *= sc[1]; o[i][j2][3] *= sc[1];
            }
        }

        /* O += P V : warp m32 x n64 */
        #pragma unroll
        for (int ks = 0; ks < 8; ks++) {
            uint4 a0 = Pp[((2 * wm) * 8 + ks) * 32 + lane];
            uint4 a1 = Pp[((2 * wm + 1) * 8 + ks) * 32 + lane];
            #pragma unroll
            for (int p = 0; p < 4; p++) {
                uint4 v = Vc[((4 * wn + p) * 8 + ks) * 32 + lane];
                mma4(o[0][2 * p],     a0, v.x, v.y);
                mma4(o[0][2 * p + 1], a0, v.z, v.w);
                mma4(o[1][2 * p],     a1, v.x, v.y);
                mma4(o[1][2 * p + 1], a1, v.z, v.w);
            }
        }

        __syncthreads();
        if (t + 2 < NT) {
            uint4* Kn = smq + OK + (t & 1) * 2048;
            uint4* Vn = smq + OV + (t & 1) * 2048;
            #pragma unroll
            for (int p = 0; p < 8; p++) {
                int idx = tid + p * 256;
                cp16(sm_u32(Kn + idx), gK + (size_t)(t + 2) * 2048 + idx);
                cp16(sm_u32(Vn + idx),
                     gV + (size_t)(idx >> 8) * 16384 + (t + 2) * 256 + (idx & 255));
            }
            CP_COMMIT();
        }
    }

    /* fused epilogue: normalize, stage, write permuted A-frags to g_p slot 5 */
    __syncthreads();
    float* St = (float*)(smq + OK);   /* 128 x 132 floats */
    #pragma unroll
    for (int i = 0; i < 2; i++) {
        float inv0 = 1.f / l_[i][0], inv1 = 1.f / l_[i][1];
        int rA = wm * 32 + i * 16 + g;
        int rB = rA + 8;
        #pragma unroll
        for (int j2 = 0; j2 < 8; j2++) {
            int c = wn * 64 + j2 * 8 + 2 * tg;
            St[rA * 132 + c]     = o[i][j2][0] * inv0;
            St[rA * 132 + c + 1] = o[i][j2][1] * inv0;
            St[rB * 132 + c]     = o[i][j2][2] * inv1;
            St[rB * 132 + c + 1] = o[i][j2][3] * inv1;
        }
    }
    __syncthreads();
    {
        uint4* gp5 = (uint4*)(g_p + 5 * (size_t)SLOT);
        const int gMIb = b * 32 + qt * 8;
        #pragma unroll
        for (int kk = 0; kk < 2; kk++) {
            int ksl = wid + kk * 8;
            #pragma unroll
            for (int MI = 0; MI < 8; MI++) {
                int r = MI * 16 + g, c = ksl * 8 + tg;
                uint4 u;
                u.x = f2tf(St[r * 132 + c]);
                u.y = f2tf(St[(r + 8) * 132 + c]);
                u.z = f2tf(St[r * 132 + c + 4]);
                u.w = f2tf(St[(r + 8) * 132 + c + 4]);
                gp5[((size_t)(gMIb + MI) * 256 + (h * 16 + ksl)) * 32 + lane] = u;
            }
        }
    }
}

/* ------------------------------------------------------------------ */
extern "C" void kernel_launch(void* const* d_in, const int* in_sizes, int n_in,
                              void* d_out, int out_size)
{
    const float* x       = (const float*)d_in[0];
    const float* k_cache = (const float*)d_in[1];
    const float* v_cache = (const float*)d_in[2];
    const float* mask    = (const float*)d_in[3];
    const float* wq = (const float*)d_in[4];
    const float* bq = (const float*)d_in[5];
    const float* wk = (const float*)d_in[6];
    const float* bk = (const float*)d_in[7];
    const float* wv = (const float*)d_in[8];
    const float* bv = (const float*)d_in[9];
    const float* wo = (const float*)d_in[10];
    const float* bo = (const float*)d_in[11];

    float* out = (float*)d_out;
    long long need = (long long)MROWS * EMB + 2LL * BSZ * KVLEN * EMB;
    int write_cache = ((long long)out_size >= need) ? 1 : 0;
    float* okc = out + (size_t)MROWS * EMB;
    float* ovc = okc + (size_t)BSZ * KVLEN * EMB;

    cudaFuncSetAttribute(attn_kernel,
                         cudaFuncAttributeMaxDynamicSharedMemorySize, ATT_SMEM);
    cudaFuncSetAttribute(qkv_kernel,
                         cudaFuncAttributeMaxDynamicSharedMemorySize, GEMM_SMEM);
    cudaFuncSetAttribute(proj_kernel,
                         cudaFuncAttributeMaxDynamicSharedMemorySize, GEMM_SMEM);

    convert5_kernel<<<dim3(4096, 5), 256>>>(x, wq, wk, wv, wo);
    qkv_kernel<<<dim3(96, 16), 256, GEMM_SMEM>>>(k_cache, v_cache,
                                                 bq, bk, bv, okc, ovc, write_cache);
    permute_new_kernel<<<1024, 256>>>();
    attn_kernel<<<dim3(4, 16, BSZ + 1), 256, ATT_SMEM>>>(k_cache, v_cache, mask,
                                                         okc, ovc, write_cache);
    proj_kernel<<<dim3(16, 16), 256, GEMM_SMEM>>>(bo, out);
}

// round 10
// speedup vs baseline: 4.2977x; 1.0240x over previous
#include <cuda_runtime.h>

#define BSZ   4
#define TGT   512
#define KVLEN 4096
#define KVOLD (KVLEN - TGT)   /* 3584 */
#define EMB   2048
#define NH    16
#define HD    128
#define MROWS (BSZ * TGT)     /* 2048 */
#define SLOT  (EMB * EMB)     /* 4M u32 per matrix */
#define QSCALE 0.08838834764831845f  /* 128^-0.5 */

/* scratch (static device arrays: allocation-free per harness rules) */
__device__ float g_q[MROWS * EMB];
__device__ float g_k[MROWS * EMB];
__device__ float g_v[MROWS * EMB];
/* permuted tf32 operands: 0=x(A) 1=wq(B) 2=wk(B) 3=wv(B) 4=wo(B) 5=attn(A) */
__device__ unsigned g_p[6 * SLOT];
/* permuted tf32 KV cache, fragment layout, per (b,h): 131072 uint4 */
__device__ uint4 g_kp[64 * 131072];
__device__ uint4 g_vp[64 * 131072];

/* ---------------- helpers ---------------- */
__device__ __forceinline__ unsigned f2tf(float f) {
    unsigned u;
    asm("cvt.rna.tf32.f32 %0, %1;" : "=r"(u) : "f"(f));
    return u;
}
__device__ __forceinline__ void mma4(float c[4], const uint4& a, unsigned b0, unsigned b1) {
    asm("mma.sync.aligned.m16n8k8.row.col.f32.tf32.tf32.f32 "
        "{%0,%1,%2,%3},{%4,%5,%6,%7},{%8,%9},{%0,%1,%2,%3};"
        : "+f"(c[0]), "+f"(c[1]), "+f"(c[2]), "+f"(c[3])
        : "r"(a.x), "r"(a.y), "r"(a.z), "r"(a.w), "r"(b0), "r"(b1));
}
__device__ __forceinline__ unsigned sm_u32(const void* p) {
    return (unsigned)__cvta_generic_to_shared(p);
}
__device__ __forceinline__ void cp16(unsigned dst, const void* src) {
    asm volatile("cp.async.cg.shared.global [%0], [%1], 16;" :: "r"(dst), "l"(src));
}
#define CP_COMMIT() asm volatile("cp.async.commit_group;")
#define CP_WAIT(n)  asm volatile("cp.async.wait_group %0;" :: "n"(n))
#define BAR_PAIR(id) asm volatile("bar.sync %0, 64;" :: "r"(id) : "memory")

/* ---------------- dense-operand permute (A/B fragment layouts) ---------------- */
__device__ __forceinline__ void permute_one(const float* __restrict__ src,
                                            uint4* __restrict__ dst,
                                            unsigned gid, int btype)
{
    unsigned lane = gid & 31, KSL = (gid >> 5) & 255, MI = gid >> 13;
    unsigned g = lane >> 2, tg = lane & 3;
    const float* p = src + (size_t)(MI * 16 + g) * EMB + KSL * 8 + tg;
    float v0 = p[0], v1 = p[8 * EMB], v2 = p[4], v3 = p[8 * EMB + 4];
    uint4 u;
    if (btype) { u.x = f2tf(v0); u.y = f2tf(v2); u.z = f2tf(v1); u.w = f2tf(v3); }
    else       { u.x = f2tf(v0); u.y = f2tf(v1); u.z = f2tf(v2); u.w = f2tf(v3); }
    dst[gid] = u;
}

__global__ void __launch_bounds__(256) convert5_kernel(
    const float* __restrict__ x,  const float* __restrict__ wq,
    const float* __restrict__ wk, const float* __restrict__ wv,
    const float* __restrict__ wo)
{
    int slot = blockIdx.y;
    const float* src = (slot == 0) ? x : (slot == 1) ? wq :
                       (slot == 2) ? wk : (slot == 3) ? wv : wo;
    unsigned gid = blockIdx.x * 256 + threadIdx.x;
    permute_one(src, (uint4*)(g_p + (size_t)slot * SLOT), gid, slot != 0);
}

/* ---------------- KV tile permute helper (64 j-rows x 128 d, staged in smem) ---- */
__device__ __forceinline__ void kv_permute_tile(
    const float* __restrict__ src,   /* + row0*EMB + h*HD pre-applied */
    float* Ts, int tt, int bh, int isV, int tid)
{
    const int lane = tid & 31, g = lane >> 2, tg = lane & 3;
    __syncthreads();
    #pragma unroll
    for (int p = 0; p < 8; p++) {
        int idx = tid + p * 256;
        int r = idx >> 5, c4 = (idx & 31) << 2;
        *(float4*)&Ts[r * 132 + c4] = *(const float4*)(src + (size_t)r * EMB + c4);
    }
    __syncthreads();
    if (!isV) {
        uint4* dst = g_kp + (size_t)bh * 131072;
        #pragma unroll
        for (int p = 0; p < 8; p++) {
            int idx = tid + p * 256;
            int pi_l = idx >> 9, ksl = (idx >> 5) & 15;
            int j0 = pi_l * 16, c = ksl * 8 + tg;
            uint4 u;
            u.x = f2tf(Ts[(j0 + g) * 132 + c]);
            u.y = f2tf(Ts[(j0 + g) * 132 + c + 4]);
            u.z = f2tf(Ts[(j0 + g + 8) * 132 + c]);
            u.w = f2tf(Ts[(j0 + g + 8) * 132 + c + 4]);
            dst[(size_t)(tt * 4 + pi_l) * 512 + ksl * 32 + lane] = u;
        }
    } else {
        uint4* dst = g_vp + (size_t)bh * 131072;
        #pragma unroll
        for (int p = 0; p < 8; p++) {
            int idx = tid + p * 256;
            int pi_d = idx >> 8, kslj = (idx >> 5) & 7;
            int d0 = pi_d * 16, j0 = kslj * 8;
            uint4 u;
            u.x = f2tf(Ts[(j0 + tg) * 132 + d0 + g]);
            u.y = f2tf(Ts[(j0 + tg + 4) * 132 + d0 + g]);
            u.z = f2tf(Ts[(j0 + tg) * 132 + d0 + g + 8]);
            u.w = f2tf(Ts[(j0 + tg + 4) * 132 + d0 + g + 8]);
            dst[(size_t)pi_d * 16384 + (size_t)(tt * 8 + kslj) * 32 + lane] = u;
        }
    }
}

/* permute NEW kv region (from g_k/g_v). 1024 blocks. */
__global__ void __launch_bounds__(256) permute_new_kernel()
{
    __shared__ float Ts[64 * 132];
    int job = blockIdx.x;               /* 0..1023 */
    int isV = job >= 512;
    int jj = job & 511;
    int bh = jj >> 3, tl = jj & 7;
    int b = bh >> 4, h = bh & 15;
    const float* src = (isV ? g_v : g_k) + ((size_t)(b * TGT) + tl * 64) * EMB + h * HD;
    kv_permute_tile(src, Ts, 56 + tl, bh, isV, threadIdx.x);
}

/* ---------------- dense GEMM: C[128,128] = A @ B^T, pre-permuted tf32 ---------------- */
#define GSTG 2048   /* uint4 per stage */
#define GEMM_SMEM (3 * GSTG * 16)

__device__ __forceinline__ void gemm_main(
    const uint4* __restrict__ Ag, const uint4* __restrict__ Bg,
    float c[4][4][4], uint4* S, int tid)
{
    const int lane = tid & 31, wid = tid >> 5;
    const int wm = wid >> 2, wn = wid & 3;

    for (int st = 0; st < 2; st++) {
        for (int i = 0; i < 8; i++) {
            int ch = tid + i * 256;
            int half = ch >> 10, cc = ch & 1023;
            int mi = cc >> 7, rest = cc & 127;
            const uint4* src = (half ? Bg : Ag) + (size_t)mi * 8192 + st * 128 + rest;
            cp16(sm_u32(S + st * GSTG + half * 1024 + cc), src);
        }
        CP_COMMIT();
    }

    for (int kt = 0; kt < 64; kt++) {
        if (kt < 63) CP_WAIT(1); else CP_WAIT(0);
        __syncthreads();

        if (kt + 2 < 64) {
            int st = (kt + 2) % 3;
            for (int i = 0; i < 8; i++) {
                int ch = tid + i * 256;
                int half = ch >> 10, cc = ch & 1023;
                int mi = cc >> 7, rest = cc & 127;
                const uint4* src = (half ? Bg : Ag) + (size_t)mi * 8192 + (kt + 2) * 128 + rest;
                cp16(sm_u32(S + st * GSTG + half * 1024 + cc), src);
            }
            CP_COMMIT();
        }

        const uint4* Af = S + (kt % 3) * GSTG;
        const uint4* Bf = Af + 1024;
        #pragma unroll
        for (int ks = 0; ks < 4; ks++) {
            uint4 a[4], bu[2];
            #pragma unroll
            for (int mt = 0; mt < 4; mt++)
                a[mt] = Af[((wm * 4 + mt) * 4 + ks) * 32 + lane];
            #pragma unroll
            for (int p = 0; p < 2; p++)
                bu[p] = Bf[((wn * 2 + p) * 4 + ks) * 32 + lane];
            #pragma unroll
            for (int mt = 0; mt < 4; mt++) {
                mma4(c[mt][0], a[mt], bu[0].x, bu[0].y);
                mma4(c[mt][1], a[mt], bu[0].z, bu[0].w);
                mma4(c[mt][2], a[mt], bu[1].x, bu[1].y);
                mma4(c[mt][3], a[mt], bu[1].z, bu[1].w);
            }
        }
    }
}

/* Fused QKV + interleaved old-KV permute plane.
   grid (96,16): x<48 -> gemm (sel = x>>4, nblk = x&15); x>=48 -> permute jobs. */
__global__ void __launch_bounds__(256, 2) qkv_kernel(
    const float* __restrict__ kc_in, const float* __restrict__ vc_in,
    const float* __restrict__ bq, const float* __restrict__ bk,
    const float* __restrict__ bv,
    float* __restrict__ okc, float* __restrict__ ovc, int write_cache)
{
    extern __shared__ uint4 S[];
    const int tid = threadIdx.x;

    if (blockIdx.x >= 48) {
        float* Ts = (float*)S;
        int pbid = (blockIdx.x - 48) + 48 * blockIdx.y;
        for (int job = pbid; job < 7168; job += 768) {
            int isV = job >= 3584;
            int jj = isV ? job - 3584 : job;
            int bh = jj / 56, tt = jj % 56;
            int b = bh >> 4, h = bh & 15;
            const float* src = (isV ? vc_in : kc_in)
                + ((size_t)(b * KVLEN) + tt * 64) * EMB + h * HD;
            kv_permute_tile(src, Ts, tt, bh, isV, tid);
        }
        return;
    }

    const int lane = tid & 31, wid = tid >> 5;
    const int g = lane >> 2, tg = lane & 3;
    const int wm = wid >> 2, wn = wid & 3;
    const int nb = blockIdx.x, mb = blockIdx.y;
    const int sel = nb >> 4, nblk = nb & 15;
    const float* bias = (sel == 0) ? bq : (sel == 1) ? bk : bv;

    const uint4* Ag = (const uint4*)(g_p) + (size_t)(mb * 8) * 8192;
    const uint4* Bg = (const uint4*)(g_p + (size_t)(1 + sel) * SLOT) + (size_t)(nblk * 8) * 8192;

    float c[4][4][4] = {};
    gemm_main(Ag, Bg, c, S, tid);

    #pragma unroll
    for (int mt = 0; mt < 4; mt++) {
        #pragma unroll
        for (int nt = 0; nt < 4; nt++) {
            int col = nblk * 128 + wn * 32 + nt * 8 + 2 * tg;
            #pragma unroll
            for (int half = 0; half < 2; half++) {
                int m = mb * 128 + wm * 64 + mt * 16 + g + half * 8;
                float v0 = c[mt][nt][half * 2 + 0] + bias[col];
                float v1 = c[mt][nt][half * 2 + 1] + bias[col + 1];
                if (sel == 0) {
                    g_q[(size_t)m * EMB + col]     = v0 * QSCALE;
                    g_q[(size_t)m * EMB + col + 1] = v1 * QSCALE;
                } else {
                    float* dst = (sel == 1) ? g_k : g_v;
                    dst[(size_t)m * EMB + col]     = v0;
                    dst[(size_t)m * EMB + col + 1] = v1;
                    if (write_cache) {
                        int bidx = m >> 9, t = m & 511;
                        float* cd = (sel == 1) ? okc : ovc;
                        size_t o = ((size_t)bidx * KVLEN + KVOLD + t) * EMB + col;
                        cd[o] = v0; cd[o + 1] = v1;
                    }
                }
            }
        }
    }
}

/* Output projection: grid (16,16). A = permuted attn (slot 5). */
__global__ void __launch_bounds__(256, 2) proj_kernel(
    const float* __restrict__ bo, float* __restrict__ out)
{
    extern __shared__ uint4 S[];
    const int tid = threadIdx.x;
    const int lane = tid & 31, wid = tid >> 5;
    const int g = lane >> 2, tg = lane & 3;
    const int wm = wid >> 2, wn = wid & 3;
    const int nblk = blockIdx.x, mb = blockIdx.y;

    const uint4* Ag = (const uint4*)(g_p + 5 * (size_t)SLOT) + (size_t)(mb * 8) * 8192;
    const uint4* Bg = (const uint4*)(g_p + 4 * (size_t)SLOT) + (size_t)(nblk * 8) * 8192;

    float c[4][4][4] = {};
    gemm_main(Ag, Bg, c, S, tid);

    #pragma unroll
    for (int mt = 0; mt < 4; mt++)
        #pragma unroll
        for (int nt = 0; nt < 4; nt++) {
            int col = nblk * 128 + wn * 32 + nt * 8 + 2 * tg;
            #pragma unroll
            for (int half = 0; half < 2; half++) {
                int m = mb * 128 + wm * 64 + mt * 16 + g + half * 8;
                out[(size_t)m * EMB + col]     = c[mt][nt][half * 2 + 0] + bo[col];
                out[(size_t)m * EMB + col + 1] = c[mt][nt][half * 2 + 1] + bo[col + 1];
            }
        }
}

/* ---------------- flash attention: deferred-PV pipeline ----------------
   256 thr, 8 warps (4 wm x 2 wn). S m32n32, PV m32n64.
   Iteration t issues: S(t) MMAs, then PV(t-1) MMAs, then softmax(t).
   The softmax stalls on S(t)'s scoreboard while PV(t-1) drains the tensor
   pipe in the background (in-order issue, out-of-order completion).
   V prefetch is shifted one iter later than K (V(t) issued at t, used t+1),
   so the 2-buffer layout is unchanged: 14336 uint4 = 229376 B. */
#define OQ 0
#define OK 4096
#define OV 8192
#define OP 12288
#define ATT_SMEM (14336 * 16)
#define NT (KVLEN / 64)

__global__ void __launch_bounds__(256, 1) attn_kernel(
    const float* __restrict__ kc_in, const float* __restrict__ vc_in,
    const float* __restrict__ mask,
    float* __restrict__ okc, float* __restrict__ ovc, int write_cache)
{
    if (blockIdx.z == BSZ) {
        if (write_cache) {
            const int cb = blockIdx.x + gridDim.x * blockIdx.y;   /* 0..63 */
            const int N4 = KVOLD * EMB / 4;
            #pragma unroll 1
            for (int b = 0; b < BSZ; b++) {
                const float4* sk = (const float4*)(kc_in + (size_t)b * KVLEN * EMB);
                const float4* sv = (const float4*)(vc_in + (size_t)b * KVLEN * EMB);
                float4* dk = (float4*)(okc + (size_t)b * KVLEN * EMB);
                float4* dv = (float4*)(ovc + (size_t)b * KVLEN * EMB);
                for (int i = cb * 256 + (int)threadIdx.x; i < N4; i += 64 * 256) {
                    dk[i] = sk[i];
                    dv[i] = sv[i];
                }
            }
        }
        return;
    }

    extern __shared__ uint4 smq[];
    uint4* Qp = smq + OQ;
    uint4* Pp = smq + OP;
    __shared__ float pmax[2][128], psum[2][128];

    const int tid  = threadIdx.x;
    const int lane = tid & 31, wid = tid >> 5;
    const int g = lane >> 2, tg = lane & 3;
    const int wm = wid >> 1, wn = wid & 1;
    const int qt = blockIdx.x, h = blockIdx.y, b = blockIdx.z;

    const uint4* gK = g_kp + (size_t)(b * 16 + h) * 131072;
    const uint4* gV = g_vp + (size_t)(b * 16 + h) * 131072;
    const float* mbase = mask + (size_t)(qt * 128) * KVLEN;

    /* prologue: issue group { K(0) } */
    #pragma unroll
    for (int p = 0; p < 8; p++) {
        int idx = tid + p * 256;
        cp16(sm_u32(smq + OK + idx), gK + idx);
    }
    CP_COMMIT();

    /* Q load + permute */
    {
        const float* qb = g_q + (size_t)(b * TGT + qt * 128) * EMB + h * HD;
        #pragma unroll
        for (int q = 0; q < 16; q++) {
            int G = wid * 16 + q;
            int mi = G >> 4, ksl = G & 15;
            const float* p = qb + (size_t)(mi * 16 + g) * EMB + ksl * 8 + tg;
            uint4 u;
            u.x = f2tf(p[0]); u.y = f2tf(p[8 * EMB]);
            u.z = f2tf(p[4]); u.w = f2tf(p[8 * EMB + 4]);
            Qp[G * 32 + lane] = u;
        }
    }

    float m_[2][2], l_[2][2];
    #pragma unroll
    for (int i = 0; i < 2; i++)
        #pragma unroll
        for (int hh = 0; hh < 2; hh++) { m_[i][hh] = -1e30f; l_[i][hh] = 0.f; }
    float o[2][8][4] = {};

    #pragma unroll 1
    for (int t = 0; t < NT; t++) {
        /* mask prefetch (global latency overlapped with cp wait) */
        float2 mk[2][2][4];
        #pragma unroll
        for (int i = 0; i < 2; i++)
            #pragma unroll
            for (int hh = 0; hh < 2; hh++) {
                int r = wm * 32 + i * 16 + hh * 8 + g;
                #pragma unroll
                for (int j = 0; j < 4; j++)
                    mk[i][hh][j] = *(const float2*)(mbase + (size_t)r * KVLEN
                                                    + t * 64 + wn * 32 + j * 8 + 2 * tg);
            }

        CP_WAIT(0);          /* group(t-1): K(t) + V(t-1) ready */
        __syncthreads();     /* publish; all prior-iter smem reads retired */

        /* issue group(t): K(t+1) -> slot (t+1)&1, V(t) -> slot t&1 */
        if (t + 1 < NT) {
            #pragma unroll
            for (int p = 0; p < 8; p++) {
                int idx = tid + p * 256;
                cp16(sm_u32(smq + OK + ((t + 1) & 1) * 2048 + idx),
                     gK + (size_t)(t + 1) * 2048 + idx);
            }
        }
        #pragma unroll
        for (int p = 0; p < 8; p++) {
            int idx = tid + p * 256;
            cp16(sm_u32(smq + OV + (t & 1) * 2048 + idx),
                 gV + (size_t)(idx >> 8) * 16384 + t * 256 + (idx & 255));
        }
        CP_COMMIT();

        const uint4* Kc = smq + OK + (t & 1) * 2048;

        /* S(t) = Q K^T : warp m32 x n32 */
        float s[2][4][4] = {};
        #pragma unroll
        for (int ks = 0; ks < 16; ks++) {
            uint4 a0 = Qp[((2 * wm) * 16 + ks) * 32 + lane];
            uint4 a1 = Qp[((2 * wm + 1) * 16 + ks) * 32 + lane];
            uint4 b0 = Kc[((2 * wn) * 16 + ks) * 32 + lane];
            uint4 b1 = Kc[((2 * wn + 1) * 16 + ks) * 32 + lane];
            mma4(s[0][0], a0, b0.x, b0.y); mma4(s[0][1], a0, b0.z, b0.w);
            mma4(s[0][2], a0, b1.x, b1.y); mma4(s[0][3], a0, b1.z, b1.w);
            mma4(s[1][0], a1, b0.x, b0.y); mma4(s[1][1], a1, b0.z, b0.w);
            mma4(s[1][2], a1, b1.x, b1.y); mma4(s[1][3], a1, b1.z, b1.w);
        }

        /* PV(t-1): queued behind S(t); executes under the softmax below */
        if (t > 0) {
            const uint4* Vc = smq + OV + ((t & 1) ^ 1) * 2048;
            #pragma unroll
            for (int ks = 0; ks < 8; ks++) {
                uint4 a0 = Pp[((2 * wm) * 8 + ks) * 32 + lane];
                uint4 a1 = Pp[((2 * wm + 1) * 8 + ks) * 32 + lane];
                #pragma unroll
                for (int p = 0; p < 4; p++) {
                    uint4 v = Vc[((4 * wn + p) * 8 + ks) * 32 + lane];
                    mma4(o[0][2 * p],     a0, v.x, v.y);
                    mma4(o[0][2 * p + 1], a0, v.z, v.w);
                    mma4(o[1][2 * p],     a1, v.x, v.y);
                    mma4(o[1][2 * p + 1], a1, v.z, v.w);
                }
            }
        }

        /* softmax(t): first read of s waits on S(t) scoreboard while the
           PV(t-1) HMMAs drain the tensor pipe */
        float mx[2][2];
        #pragma unroll
        for (int i = 0; i < 2; i++) {
            mx[i][0] = -1e30f; mx[i][1] = -1e30f;
            #pragma unroll
            for (int j = 0; j < 4; j++) {
                s[i][j][0] += mk[i][0][j].x; s[i][j][1] += mk[i][0][j].y;
                s[i][j][2] += mk[i][1][j].x; s[i][j][3] += mk[i][1][j].y;
                mx[i][0] = fmaxf(mx[i][0], fmaxf(s[i][j][0], s[i][j][1]));
                mx[i][1] = fmaxf(mx[i][1], fmaxf(s[i][j][2], s[i][j][3]));
            }
            mx[i][0] = fmaxf(mx[i][0], __shfl_xor_sync(0xffffffffu, mx[i][0], 1));
            mx[i][0] = fmaxf(mx[i][0], __shfl_xor_sync(0xffffffffu, mx[i][0], 2));
            mx[i][1] = fmaxf(mx[i][1], __shfl_xor_sync(0xffffffffu, mx[i][1], 1));
            mx[i][1] = fmaxf(mx[i][1], __shfl_xor_sync(0xffffffffu, mx[i][1], 2));
        }
        if (tg == 0) {
            #pragma unroll
            for (int i = 0; i < 2; i++) {
                pmax[wn][wm * 32 + i * 16 + g]     = mx[i][0];
                pmax[wn][wm * 32 + i * 16 + 8 + g] = mx[i][1];
            }
        }
        BAR_PAIR(1 + wm);   /* also orders pair's PV Pp-reads before Pp(t) writes */

        float mn[2][2], ss[2][2];
        unsigned* Pu = (unsigned*)Pp;
        const int eoff = (g * 4 + (tg & 1) * 2) * 4 + (tg >> 1) * 2;
        #pragma unroll
        for (int i = 0; i < 2; i++) {
            #pragma unroll
            for (int hh = 0; hh < 2; hh++) {
                int r = wm * 32 + i * 16 + hh * 8 + g;
                mn[i][hh] = fmaxf(m_[i][hh], fmaxf(pmax[0][r], pmax[1][r]));
                ss[i][hh] = 0.f;
            }
            #pragma unroll
            for (int j = 0; j < 4; j++) {
                s[i][j][0] = __expf(s[i][j][0] - mn[i][0]);
                s[i][j][1] = __expf(s[i][j][1] - mn[i][0]);
                s[i][j][2] = __expf(s[i][j][2] - mn[i][1]);
                s[i][j][3] = __expf(s[i][j][3] - mn[i][1]);
                ss[i][0] += s[i][j][0] + s[i][j][1];
                ss[i][1] += s[i][j][2] + s[i][j][3];
                int bb = ((2 * wm + i) * 8 + 4 * wn + j) * 128 + eoff;
                Pu[bb + 0] = f2tf(s[i][j][0]);
                Pu[bb + 4] = f2tf(s[i][j][1]);
                Pu[bb + 1] = f2tf(s[i][j][2]);
                Pu[bb + 5] = f2tf(s[i][j][3]);
            }
            #pragma unroll
            for (int hh = 0; hh < 2; hh++) {
                ss[i][hh] += __shfl_xor_sync(0xffffffffu, ss[i][hh], 1);
                ss[i][hh] += __shfl_xor_sync(0xffffffffu, ss[i][hh], 2);
            }
        }
        if (tg == 0) {
            #pragma unroll
            for (int i = 0; i < 2; i++) {
                psum[wn][wm * 32 + i * 16 + g]     = ss[i][0];
                psum[wn][wm * 32 + i * 16 + 8 + g] = ss[i][1];
            }
        }
        BAR_PAIR(1 + wm);

        /* update stats; scale o (waits on PV(t-1) completion via scoreboard) */
        #pragma unroll
        for (int i = 0; i < 2; i++) {
            float sc[2];
            #pragma unroll
            for (int hh = 0; hh < 2; hh++) {
                int r = wm * 32 + i * 16 + hh * 8 + g;
                sc[hh] = __expf(m_[i][hh] - mn[i][hh]);
                l_[i][hh] = l_[i][hh] * sc[hh] + psum[0][r] + psum[1][r];
                m_[i][hh] = mn[i][hh];
            }
            #pragma unroll
            for (int j2 = 0; j2 < 8; j2++) {
                o[i][j2][0] *= sc[0]; o[i][j2][1] *= sc[0];
                o[i][j2][2] *= sc[1]; o[i][j2][3] *= sc[1];
            }
        }
    }

    /* drain: PV(NT-1) */
    CP_WAIT(0);
    __syncthreads();
    {
        const uint4* Vc = smq + OV + ((NT - 1) & 1) * 2048;
        #pragma unroll
        for (int ks = 0; ks < 8; ks++) {
            uint4 a0 = Pp[((2 * wm) * 8 + ks) * 32 + lane];
            uint4 a1 = Pp[((2 * wm + 1) * 8 + ks) * 32 + lane];
            #pragma unroll
            for (int p = 0; p < 4; p++) {
                uint4 v = Vc[((4 * wn + p) * 8 + ks) * 32 + lane];
                mma4(o[0][2 * p],     a0, v.x, v.y);
                mma4(o[0][2 * p + 1], a0, v.z, v.w);
                mma4(o[1][2 * p],     a1, v.x, v.y);
                mma4(o[1][2 * p + 1], a1, v.z, v.w);
            }
        }
    }

    /* fused epilogue: normalize, stage, write permuted A-frags to g_p slot 5 */
    __syncthreads();
    float* St = (float*)(smq + OK);   /* 128 x 132 floats */
    #pragma unroll
    for (int i = 0; i < 2; i++) {
        float inv0 = 1.f / l_[i][0], inv1 = 1.f / l_[i][1];
        int rA = wm * 32 + i * 16 + g;
        int rB = rA + 8;
        #pragma unroll
        for (int j2 = 0; j2 < 8; j2++) {
            int c = wn * 64 + j2 * 8 + 2 * tg;
            St[rA * 132 + c]     = o[i][j2][0] * inv0;
            St[rA * 132 + c + 1] = o[i][j2][1] * inv0;
            St[rB * 132 + c]     = o[i][j2][2] * inv1;
            St[rB * 132 + c + 1] = o[i][j2][3] * inv1;
        }
    }
    __syncthreads();
    {
        uint4* gp5 = (uint4*)(g_p + 5 * (size_t)SLOT);
        const int gMIb = b * 32 + qt * 8;
        #pragma unroll
        for (int kk = 0; kk < 2; kk++) {
            int ksl = wid + kk * 8;
            #pragma unroll
            for (int MI = 0; MI < 8; MI++) {
                int r = MI * 16 + g, c = ksl * 8 + tg;
                uint4 u;
                u.x = f2tf(St[r * 132 + c]);
                u.y = f2tf(St[(r + 8) * 132 + c]);
                u.z = f2tf(St[r * 132 + c + 4]);
                u.w = f2tf(St[(r + 8) * 132 + c + 4]);
                gp5[((size_t)(gMIb + MI) * 256 + (h * 16 + ksl)) * 32 + lane] = u;
            }
        }
    }
}

/* ------------------------------------------------------------------ */
extern "C" void kernel_launch(void* const* d_in, const int* in_sizes, int n_in,
                              void* d_out, int out_size)
{
    const float* x       = (const float*)d_in[0];
    const float* k_cache = (const float*)d_in[1];
    const float* v_cache = (const float*)d_in[2];
    const float* mask    = (const float*)d_in[3];
    const float* wq = (const float*)d_in[4];
    const float* bq = (const float*)d_in[5];
    const float* wk = (const float*)d_in[6];
    const float* bk = (const float*)d_in[7];
    const float* wv = (const float*)d_in[8];
    const float* bv = (const float*)d_in[9];
    const float* wo = (const float*)d_in[10];
    const float* bo = (const float*)d_in[11];

    float* out = (float*)d_out;
    long long need = (long long)MROWS * EMB + 2LL * BSZ * KVLEN * EMB;
    int write_cache = ((long long)out_size >= need) ? 1 : 0;
    float* okc = out + (size_t)MROWS * EMB;
    float* ovc = okc + (size_t)BSZ * KVLEN * EMB;

    cudaFuncSetAttribute(attn_kernel,
                         cudaFuncAttributeMaxDynamicSharedMemorySize, ATT_SMEM);
    cudaFuncSetAttribute(qkv_kernel,
                         cudaFuncAttributeMaxDynamicSharedMemorySize, GEMM_SMEM);
    cudaFuncSetAttribute(proj_kernel,
                         cudaFuncAttributeMaxDynamicSharedMemorySize, GEMM_SMEM);

    convert5_kernel<<<dim3(4096, 5), 256>>>(x, wq, wk, wv, wo);
    qkv_kernel<<<dim3(96, 16), 256, GEMM_SMEM>>>(k_cache, v_cache,
                                                 bq, bk, bv, okc, ovc, write_cache);
    permute_new_kernel<<<1024, 256>>>();
    attn_kernel<<<dim3(4, 16, BSZ + 1), 256, ATT_SMEM>>>(k_cache, v_cache, mask,
                                                         okc, ovc, write_cache);
    proj_kernel<<<dim3(16, 16), 256, GEMM_SMEM>>>(bo, out);
}